// round 1
// baseline (speedup 1.0000x reference)
#include <cuda_runtime.h>
#include <cuda_bf16.h>
#include <math.h>

// ---------------------------------------------------------------------------
// GPT forward, fp32 SIMT baseline.
// B=4, T=512, K=512, H=8, NB=4, VOCAB=32000. M = B*T = 2048 tokens.
// ---------------------------------------------------------------------------

#define BATCH 4
#define SEQ   512
#define KD    512
#define HEADS 8
#define NBLK  4
#define VOCAB 32000
#define MTOK  (BATCH*SEQ)        // 2048
#define HK    (HEADS*KD)         // 4096
#define FF    (4*KD)             // 2048

// Scratch (device globals; no allocation allowed)
__device__ float g_h  [MTOK*KD];        // hidden state          4 MB
__device__ float g_q  [MTOK*HK];        // Q                    33.5 MB
__device__ float g_k  [MTOK*HK];        // K
__device__ float g_v  [MTOK*HK];        // V
__device__ float g_att[BATCH*HEADS*SEQ*SEQ]; // scores/att       33.5 MB
__device__ float g_y  [MTOK*HK];        // attention out concat
__device__ float g_tmp[MTOK*KD];        // proj / mlp out        4 MB
__device__ float g_ff [MTOK*FF];        // gelu intermediate    16.8 MB

// ---------------------------------------------------------------------------
// Generic tiled GEMM: C = A(MxK) * op(B) (+bias)(+gelu)
//  TRANSB=0: B is [K,N] row-major (ldb). TRANSB=1: B is [N,K] row-major (ldb).
//  EPI: 0 none, 1 +bias, 2 gelu(x+bias)
//  Batched via blockIdx.z: zb=z/zdiv, zh=z%zdiv; ptr += zb*xO + zh*xI
// Tile: 128x128x8, 256 threads, 8x8 per thread (split-64 fragment layout).
// Requires M%128==0, N%128==0, K%8==0, all lds %4==0.
// ---------------------------------------------------------------------------
template<int TRANSB, int EPI>
__global__ __launch_bounds__(256, 2)
void gemm_k(const float* __restrict__ A, const float* __restrict__ B,
            const float* __restrict__ bias, float* __restrict__ C,
            int M, int N, int K, int lda, int ldb, int ldc,
            long aO, long aI, long bO, long bI, long cO, long cI, int zdiv)
{
    const int z  = blockIdx.z;
    const int zb = z / zdiv, zh = z - zb * zdiv;
    A += (size_t)zb * aO + (size_t)zh * aI;
    B += (size_t)zb * bO + (size_t)zh * bI;
    C += (size_t)zb * cO + (size_t)zh * cI;

    __shared__ float As[8][132];
    __shared__ float Bs[8][132];

    const int tid = threadIdx.x;
    const int tx  = tid & 15;          // 0..15 -> column fragment
    const int ty  = tid >> 4;          // 0..15 -> row fragment
    const int bx  = blockIdx.x, by = blockIdx.y;

    // A tile loader: each thread loads one float4 along K
    const int ar = tid >> 1;           // 0..127 row within tile
    const int ak = (tid & 1) << 2;     // 0 or 4
    // B tile loader (NN): one float4 along N
    const int bk = tid >> 5;           // 0..7
    const int bn = (tid & 31) << 2;    // 0..124

    const float* Aptr  = A + (size_t)(by * 128 + ar) * lda + ak;
    const float* BptrT = B + (size_t)(bx * 128 + ar) * ldb + ak;
    const float* BptrN = B + (size_t)bk * ldb + bx * 128 + bn;

    float acc[8][8];
    #pragma unroll
    for (int i = 0; i < 8; i++)
        #pragma unroll
        for (int j = 0; j < 8; j++) acc[i][j] = 0.f;

    for (int k0 = 0; k0 < K; k0 += 8) {
        float4 a4 = *(const float4*)(Aptr + k0);
        As[ak+0][ar] = a4.x; As[ak+1][ar] = a4.y;
        As[ak+2][ar] = a4.z; As[ak+3][ar] = a4.w;
        if (TRANSB) {
            float4 b4 = *(const float4*)(BptrT + k0);
            Bs[ak+0][ar] = b4.x; Bs[ak+1][ar] = b4.y;
            Bs[ak+2][ar] = b4.z; Bs[ak+3][ar] = b4.w;
        } else {
            float4 b4 = *(const float4*)(BptrN + (size_t)k0 * ldb);
            *(float4*)&Bs[bk][bn] = b4;
        }
        __syncthreads();
        #pragma unroll
        for (int kk = 0; kk < 8; kk++) {
            float a[8], b[8];
            *(float4*)(a)     = *(const float4*)&As[kk][ty * 4];
            *(float4*)(a + 4) = *(const float4*)&As[kk][64 + ty * 4];
            *(float4*)(b)     = *(const float4*)&Bs[kk][tx * 4];
            *(float4*)(b + 4) = *(const float4*)&Bs[kk][64 + tx * 4];
            #pragma unroll
            for (int i = 0; i < 8; i++)
                #pragma unroll
                for (int j = 0; j < 8; j++)
                    acc[i][j] = fmaf(a[i], b[j], acc[i][j]);
        }
        __syncthreads();
    }

    const int col0 = bx * 128 + tx * 4;
    #pragma unroll
    for (int ih = 0; ih < 2; ih++) {
        #pragma unroll
        for (int ii = 0; ii < 4; ii++) {
            const int i   = ih * 4 + ii;
            const int row = by * 128 + ih * 64 + ty * 4 + ii;
            #pragma unroll
            for (int jh = 0; jh < 2; jh++) {
                float4 o;
                float* po = &o.x;
                #pragma unroll
                for (int jj = 0; jj < 4; jj++) {
                    float v = acc[i][jh * 4 + jj];
                    if (EPI >= 1) v += bias[col0 + jh * 64 + jj];
                    if (EPI == 2) v = 0.5f * v * (1.0f + erff(v * 0.7071067811865475f));
                    po[jj] = v;
                }
                *(float4*)&C[(size_t)row * ldc + col0 + jh * 64] = o;
            }
        }
    }
}

// ---------------------------------------------------------------------------
// Embedding + positional encoding. One block per token, 256 threads.
// pos(t,c): j=c/2, ang = t * 10000^{-j/128}; even->sin, odd->cos
// ---------------------------------------------------------------------------
__global__ void embed_k(const int* __restrict__ x, const float* __restrict__ W,
                        float* __restrict__ h)
{
    const int token = blockIdx.x;
    const int t  = token & (SEQ - 1);
    const int id = x[token];
    const int tid = threadIdx.x;
    #pragma unroll
    for (int u = 0; u < 2; u++) {
        const int c = tid + u * 256;
        const int j = c >> 1;
        // log(10000)/128 = 0.07195578415606394
        const float ang = (float)t * expf(-(float)j * 0.07195578415606394f);
        const float p = (c & 1) ? cosf(ang) : sinf(ang);
        h[(size_t)token * KD + c] = W[(size_t)id * KD + c] + p;
    }
}

// ---------------------------------------------------------------------------
// Causal softmax over scores rows (scale folded in). grid(SEQ, B*H), 256 thr.
// ---------------------------------------------------------------------------
__global__ void softmax_k(float* __restrict__ att)
{
    const int q  = blockIdx.x;
    const int bh = blockIdx.y;
    float* row = att + ((size_t)bh * SEQ + q) * SEQ;
    const int tid = threadIdx.x;
    const float scale = 0.04419417382415922f;  // 1/sqrt(512)
    __shared__ float red[256];

    const float s0 = (tid       <= q) ? row[tid]       * scale : -3.4e38f;
    const float s1 = (tid + 256 <= q) ? row[tid + 256] * scale : -3.4e38f;
    red[tid] = fmaxf(s0, s1);
    __syncthreads();
    for (int o = 128; o; o >>= 1) {
        if (tid < o) red[tid] = fmaxf(red[tid], red[tid + o]);
        __syncthreads();
    }
    const float m = red[0];
    __syncthreads();
    const float v0 = (tid       <= q) ? expf(s0 - m) : 0.f;
    const float v1 = (tid + 256 <= q) ? expf(s1 - m) : 0.f;
    red[tid] = v0 + v1;
    __syncthreads();
    for (int o = 128; o; o >>= 1) {
        if (tid < o) red[tid] += red[tid + o];
        __syncthreads();
    }
    const float inv = 1.0f / red[0];
    row[tid]       = v0 * inv;
    row[tid + 256] = v1 * inv;
}

// ---------------------------------------------------------------------------
// (optional residual) + LayerNorm. One block per token, 256 threads.
// h = LN(src + (residual? h : 0)) * w + b
// ---------------------------------------------------------------------------
__global__ void ln_k(const float* __restrict__ src, float* __restrict__ h,
                     const float* __restrict__ w, const float* __restrict__ b,
                     int residual)
{
    const int token = blockIdx.x;
    const size_t base = (size_t)token * KD;
    const int tid = threadIdx.x;
    float x0 = src[base + tid];
    float x1 = src[base + tid + 256];
    if (residual) { x0 += h[base + tid]; x1 += h[base + tid + 256]; }
    __shared__ float s1[256], s2[256];
    s1[tid] = x0 + x1;
    s2[tid] = x0 * x0 + x1 * x1;
    __syncthreads();
    for (int o = 128; o; o >>= 1) {
        if (tid < o) { s1[tid] += s1[tid + o]; s2[tid] += s2[tid + o]; }
        __syncthreads();
    }
    const float mean = s1[0] * (1.f / KD);
    const float var  = s2[0] * (1.f / KD) - mean * mean;
    const float r = rsqrtf(var + 1e-5f);
    h[base + tid]       = (x0 - mean) * r * w[tid]       + b[tid];
    h[base + tid + 256] = (x1 - mean) * r * w[tid + 256] + b[tid + 256];
}

// ---------------------------------------------------------------------------
// Host-side launcher
// ---------------------------------------------------------------------------
static inline void run_gemm(int transb, int epi,
                            const float* A, const float* B, const float* bias, float* C,
                            int M, int N, int K, int lda, int ldb, int ldc,
                            long aO, long aI, long bO, long bI, long cO, long cI,
                            int zdiv, int batches)
{
    dim3 grid(N / 128, M / 128, batches), block(256);
    if (transb) {
        gemm_k<1, 0><<<grid, block>>>(A, B, bias, C, M, N, K, lda, ldb, ldc,
                                      aO, aI, bO, bI, cO, cI, zdiv);
    } else if (epi == 0) {
        gemm_k<0, 0><<<grid, block>>>(A, B, bias, C, M, N, K, lda, ldb, ldc,
                                      aO, aI, bO, bI, cO, cI, zdiv);
    } else if (epi == 1) {
        gemm_k<0, 1><<<grid, block>>>(A, B, bias, C, M, N, K, lda, ldb, ldc,
                                      aO, aI, bO, bI, cO, cI, zdiv);
    } else {
        gemm_k<0, 2><<<grid, block>>>(A, B, bias, C, M, N, K, lda, ldb, ldc,
                                      aO, aI, bO, bI, cO, cI, zdiv);
    }
}

extern "C" void kernel_launch(void* const* d_in, const int* in_sizes, int n_in,
                              void* d_out, int out_size)
{
    const int*   x        = (const int*)  d_in[0];
    const float* embed_W  = (const float*)d_in[1];
    const float* Wq       = (const float*)d_in[2];
    const float* Wk       = (const float*)d_in[3];
    const float* Wv       = (const float*)d_in[4];
    const float* Wu       = (const float*)d_in[5];
    const float* bu       = (const float*)d_in[6];
    const float* W1       = (const float*)d_in[7];
    const float* b1       = (const float*)d_in[8];
    const float* W2       = (const float*)d_in[9];
    const float* b2       = (const float*)d_in[10];
    const float* ln1_w    = (const float*)d_in[11];
    const float* ln1_b    = (const float*)d_in[12];
    const float* ln2_w    = (const float*)d_in[13];
    const float* ln2_b    = (const float*)d_in[14];
    const float* lnf_w    = (const float*)d_in[15];
    const float* lnf_b    = (const float*)d_in[16];
    const float* unembedW = (const float*)d_in[17];
    const float* unembedB = (const float*)d_in[18];
    float* out = (float*)d_out;

    float *h, *q, *k, *v, *att, *y, *tmp, *ff;
    cudaGetSymbolAddress((void**)&h,   g_h);
    cudaGetSymbolAddress((void**)&q,   g_q);
    cudaGetSymbolAddress((void**)&k,   g_k);
    cudaGetSymbolAddress((void**)&v,   g_v);
    cudaGetSymbolAddress((void**)&att, g_att);
    cudaGetSymbolAddress((void**)&y,   g_y);
    cudaGetSymbolAddress((void**)&tmp, g_tmp);
    cudaGetSymbolAddress((void**)&ff,  g_ff);

    // 1) embedding + positional encoding
    embed_k<<<MTOK, 256>>>(x, embed_W, h);

    const long bhO = (long)SEQ * HK;   // batch stride in q/k/v/y (t-major, 4096 per row)
    const long hdI = (long)KD;         // head stride within a row
    const long atO = (long)HEADS * SEQ * SEQ;  // att batch stride
    const long atI = (long)SEQ * SEQ;          // att head stride

    for (int i = 0; i < NBLK; i++) {
        const float* Wq_i = Wq + (size_t)i * KD * HK;
        const float* Wk_i = Wk + (size_t)i * KD * HK;
        const float* Wv_i = Wv + (size_t)i * KD * HK;
        const float* Wu_i = Wu + (size_t)i * HK * KD;
        const float* bu_i = bu + (size_t)i * KD;
        const float* W1_i = W1 + (size_t)i * KD * FF;
        const float* b1_i = b1 + (size_t)i * FF;
        const float* W2_i = W2 + (size_t)i * FF * KD;
        const float* b2_i = b2 + (size_t)i * KD;

        // QKV projections: [2048,512] @ [512,4096]
        run_gemm(0, 0, h, Wq_i, nullptr, q, MTOK, HK, KD, KD, HK, HK,
                 0, 0, 0, 0, 0, 0, 1, 1);
        run_gemm(0, 0, h, Wk_i, nullptr, k, MTOK, HK, KD, KD, HK, HK,
                 0, 0, 0, 0, 0, 0, 1, 1);
        run_gemm(0, 0, h, Wv_i, nullptr, v, MTOK, HK, KD, KD, HK, HK,
                 0, 0, 0, 0, 0, 0, 1, 1);

        // scores = Q @ K^T (batched over b*h = 32); softmax folds the 1/sqrt(d) scale
        run_gemm(1, 0, q, k, nullptr, att, SEQ, SEQ, KD, HK, HK, SEQ,
                 bhO, hdI, bhO, hdI, atO, atI, HEADS, BATCH * HEADS);

        softmax_k<<<dim3(SEQ, BATCH * HEADS), 256>>>(att);

        // y = att @ V (batched)
        run_gemm(0, 0, att, v, nullptr, y, SEQ, SEQ, SEQ, SEQ, HK, HK,
                 (long)HEADS * atI, atI, bhO, hdI, bhO, hdI, HEADS, BATCH * HEADS);

        // attention output projection: [2048,4096] @ [4096,512] + bu
        run_gemm(0, 1, y, Wu_i, bu_i, tmp, MTOK, KD, HK, HK, KD, KD,
                 0, 0, 0, 0, 0, 0, 1, 1);

        // h = LN(tmp + h)
        ln_k<<<MTOK, 256>>>(tmp, h, ln1_w + (size_t)i * KD, ln1_b + (size_t)i * KD, 1);

        // ff = gelu(h @ W1 + b1)
        run_gemm(0, 2, h, W1_i, b1_i, ff, MTOK, FF, KD, KD, FF, FF,
                 0, 0, 0, 0, 0, 0, 1, 1);

        // tmp = ff @ W2 + b2
        run_gemm(0, 1, ff, W2_i, b2_i, tmp, MTOK, KD, FF, FF, KD, KD,
                 0, 0, 0, 0, 0, 0, 1, 1);

        // h = LN(tmp + h)
        ln_k<<<MTOK, 256>>>(tmp, h, ln2_w + (size_t)i * KD, ln2_b + (size_t)i * KD, 1);
    }

    // final LN (no residual)
    ln_k<<<MTOK, 256>>>(h, h, lnf_w, lnf_b, 0);

    // unembed: [2048,512] @ [512,32000] + bias -> out
    run_gemm(0, 1, h, unembedW, unembedB, out, MTOK, VOCAB, KD, KD, VOCAB, VOCAB,
             0, 0, 0, 0, 0, 0, 1, 1);
}

// round 3
// speedup vs baseline: 1.1488x; 1.1488x over previous
#include <cuda_runtime.h>
#include <cuda_bf16.h>
#include <math.h>

// ---------------------------------------------------------------------------
// GPT forward. Tensor-core tf32x3 GEMMs (fp32-accurate), fp32 elementwise.
// B=4, T=512, K=512, H=8, NB=4, VOCAB=32000. M = B*T = 2048 tokens.
// ---------------------------------------------------------------------------

#define BATCH 4
#define SEQ   512
#define KD    512
#define HEADS 8
#define NBLK  4
#define VOCAB 32000
#define MTOK  (BATCH*SEQ)        // 2048
#define HK    (HEADS*KD)         // 4096
#define FF    (4*KD)             // 2048

// Scratch (device globals; no allocation allowed)
__device__ float g_h  [MTOK*KD];
__device__ float g_q  [MTOK*HK];
__device__ float g_k  [MTOK*HK];
__device__ float g_v  [MTOK*HK];
__device__ float g_att[BATCH*HEADS*SEQ*SEQ];
__device__ float g_y  [MTOK*HK];
__device__ float g_tmp[MTOK*KD];
__device__ float g_ff [MTOK*FF];

// ---------------------------------------------------------------------------
// tf32 helpers
// ---------------------------------------------------------------------------
__device__ __forceinline__ float tf32_rnd(float x) {
    unsigned u;
    asm("cvt.rna.tf32.f32 %0, %1;" : "=r"(u) : "f"(x));
    return __uint_as_float(u);
}

__device__ __forceinline__ void mma8(float* c, const unsigned* a, const unsigned* b) {
    asm volatile(
        "mma.sync.aligned.m16n8k8.row.col.f32.tf32.tf32.f32 "
        "{%0,%1,%2,%3},{%4,%5,%6,%7},{%8,%9},{%0,%1,%2,%3};"
        : "+f"(c[0]), "+f"(c[1]), "+f"(c[2]), "+f"(c[3])
        : "r"(a[0]), "r"(a[1]), "r"(a[2]), "r"(a[3]), "r"(b[0]), "r"(b[1]));
}

// ---------------------------------------------------------------------------
// tf32x3 tensor-core GEMM: C = A(MxK) * op(B) (+bias)(+gelu)
//  TRANSB=0: B is [K,N] row-major. TRANSB=1: B is [N,K] row-major.
//  EPI: 0 none, 1 +bias, 2 gelu(x+bias)
//  Batched via blockIdx.z: zb=z/zdiv, zh=z%zdiv.
// Tile: 128x128x16, 256 threads (8 warps, 2x4), warp tile 64x32.
// Precision: x = hi(tf32-rna) + lo;  acc += hi*lo' + lo*hi' + hi*hi'.
// SMEM: k-major [16][136] tiles; XOR-16 swizzle on the m/n index for the
// upper k8 half -> all tile STS and all frag LDS are bank-conflict-free.
// Requires M%128==0, N%128==0, K%16==0.
// ---------------------------------------------------------------------------
template<int TRANSB, int EPI>
__global__ __launch_bounds__(256)
void gemm_tc(const float* __restrict__ A, const float* __restrict__ B,
             const float* __restrict__ bias, float* __restrict__ C,
             int M, int N, int K, int lda, int ldb, int ldc,
             long aO, long aI, long bO, long bI, long cO, long cI, int zdiv)
{
    const int z  = blockIdx.z;
    const int zb = z / zdiv, zh = z - zb * zdiv;
    A += (size_t)zb * aO + (size_t)zh * aI;
    B += (size_t)zb * bO + (size_t)zh * bI;
    C += (size_t)zb * cO + (size_t)zh * cI;

    __shared__ float As_hi[16][136], As_lo[16][136];
    __shared__ float Bs_hi[16][136], Bs_lo[16][136];

    const int tid  = threadIdx.x;
    const int lane = tid & 31;
    const int warp = tid >> 5;
    const int g    = lane >> 2;       // mma group (0..7)
    const int tc   = lane & 3;        // thread-in-group (0..3)
    const int wm   = (warp >> 2) * 64;  // warp row base in tile
    const int wn   = (warp & 3) * 32;   // warp col base in tile
    const int bx   = blockIdx.x, by = blockIdx.y;

    // A tile loader: thread -> row ar, k-half akb (0 or 8), two float4 along K
    const int ar  = tid >> 1;
    const int akb = (tid & 1) << 3;
    const int axr = ar ^ (akb << 1);          // XOR-16 swizzle for upper k8
    const float* Aptr = A + (size_t)(by * 128 + ar) * lda + akb;

    // B tile loaders
    const float* BqT = nullptr;               // TRANSB: like A (rows = n)
    const float* BnA = nullptr;               // NN: row k = warp, float4 along n
    const float* BnB = nullptr;
    int bxr = 0, bkb = 0, bkA = 0, bnA = 0, bnB = 0;
    if (TRANSB) {
        bkb = (tid & 1) << 3;
        bxr = (tid >> 1) ^ (bkb << 1);
        BqT = B + (size_t)(bx * 128 + (tid >> 1)) * ldb + bkb;
    } else {
        bkA = tid >> 5;                       // 0..7 (second pass +8)
        bnA = lane * 4;
        bnB = bnA ^ 16;                       // swizzle for k>=8 rows
        BnA = B + (size_t)bkA * ldb + bx * 128 + bnA;
        BnB = BnA + (size_t)8 * ldb;
    }

    float acc[4][4][4];
    #pragma unroll
    for (int i = 0; i < 4; i++)
        #pragma unroll
        for (int j = 0; j < 4; j++)
            #pragma unroll
            for (int r = 0; r < 4; r++) acc[i][j][r] = 0.f;

    for (int k0 = 0; k0 < K; k0 += 16) {
        // ---- stage A chunk (split hi/lo) ----
        {
            float4 u = *(const float4*)(Aptr + k0);
            float4 w = *(const float4*)(Aptr + k0 + 4);
            float v[8] = {u.x, u.y, u.z, u.w, w.x, w.y, w.z, w.w};
            #pragma unroll
            for (int j = 0; j < 8; j++) {
                float hi = tf32_rnd(v[j]);
                As_hi[akb + j][axr] = hi;
                As_lo[akb + j][axr] = v[j] - hi;
            }
        }
        // ---- stage B chunk ----
        if (TRANSB) {
            float4 u = *(const float4*)(BqT + k0);
            float4 w = *(const float4*)(BqT + k0 + 4);
            float v[8] = {u.x, u.y, u.z, u.w, w.x, w.y, w.z, w.w};
            #pragma unroll
            for (int j = 0; j < 8; j++) {
                float hi = tf32_rnd(v[j]);
                Bs_hi[bkb + j][bxr] = hi;
                Bs_lo[bkb + j][bxr] = v[j] - hi;
            }
        } else {
            float4 u = *(const float4*)(BnA + (size_t)k0 * ldb);
            float4 w = *(const float4*)(BnB + (size_t)k0 * ldb);
            float uh[4] = {tf32_rnd(u.x), tf32_rnd(u.y), tf32_rnd(u.z), tf32_rnd(u.w)};
            float wh[4] = {tf32_rnd(w.x), tf32_rnd(w.y), tf32_rnd(w.z), tf32_rnd(w.w)};
            *(float4*)&Bs_hi[bkA][bnA]     = make_float4(uh[0], uh[1], uh[2], uh[3]);
            *(float4*)&Bs_lo[bkA][bnA]     = make_float4(u.x - uh[0], u.y - uh[1], u.z - uh[2], u.w - uh[3]);
            *(float4*)&Bs_hi[bkA + 8][bnB] = make_float4(wh[0], wh[1], wh[2], wh[3]);
            *(float4*)&Bs_lo[bkA + 8][bnB] = make_float4(w.x - wh[0], w.y - wh[1], w.z - wh[2], w.w - wh[3]);
        }
        __syncthreads();

        // ---- two k8 MMA steps ----
        #pragma unroll
        for (int ks = 0; ks < 16; ks += 8) {
            const int xs = ks << 1;           // 0 or 16
            const int kc = ks + tc;
            unsigned Ah[4][4], Al[4][4], Bh[4][2], Bl[4][2];
            #pragma unroll
            for (int mf = 0; mf < 4; mf++) {
                const int mb = (wm + mf * 16 + g) ^ xs;
                Ah[mf][0] = __float_as_uint(As_hi[kc][mb]);
                Ah[mf][1] = __float_as_uint(As_hi[kc][mb + 8]);
                Ah[mf][2] = __float_as_uint(As_hi[kc + 4][mb]);
                Ah[mf][3] = __float_as_uint(As_hi[kc + 4][mb + 8]);
                Al[mf][0] = __float_as_uint(As_lo[kc][mb]);
                Al[mf][1] = __float_as_uint(As_lo[kc][mb + 8]);
                Al[mf][2] = __float_as_uint(As_lo[kc + 4][mb]);
                Al[mf][3] = __float_as_uint(As_lo[kc + 4][mb + 8]);
            }
            #pragma unroll
            for (int nf = 0; nf < 4; nf++) {
                const int nb = (wn + nf * 8 + g) ^ xs;
                Bh[nf][0] = __float_as_uint(Bs_hi[kc][nb]);
                Bh[nf][1] = __float_as_uint(Bs_hi[kc + 4][nb]);
                Bl[nf][0] = __float_as_uint(Bs_lo[kc][nb]);
                Bl[nf][1] = __float_as_uint(Bs_lo[kc + 4][nb]);
            }
            #pragma unroll
            for (int mf = 0; mf < 4; mf++)
                #pragma unroll
                for (int nf = 0; nf < 4; nf++) {
                    mma8(acc[mf][nf], Ah[mf], Bl[nf]);
                    mma8(acc[mf][nf], Al[mf], Bh[nf]);
                    mma8(acc[mf][nf], Ah[mf], Bh[nf]);
                }
        }
        __syncthreads();
    }

    // ---- epilogue ----
    #pragma unroll
    for (int mf = 0; mf < 4; mf++) {
        const int r0 = by * 128 + wm + mf * 16 + g;
        #pragma unroll
        for (int nf = 0; nf < 4; nf++) {
            const int col = bx * 128 + wn + nf * 8 + tc * 2;
            float c0 = acc[mf][nf][0], c1 = acc[mf][nf][1];
            float c2 = acc[mf][nf][2], c3 = acc[mf][nf][3];
            if (EPI >= 1) {
                const float b0v = bias[col], b1v = bias[col + 1];
                c0 += b0v; c1 += b1v; c2 += b0v; c3 += b1v;
            }
            if (EPI == 2) {
                c0 = 0.5f * c0 * (1.0f + erff(c0 * 0.7071067811865475f));
                c1 = 0.5f * c1 * (1.0f + erff(c1 * 0.7071067811865475f));
                c2 = 0.5f * c2 * (1.0f + erff(c2 * 0.7071067811865475f));
                c3 = 0.5f * c3 * (1.0f + erff(c3 * 0.7071067811865475f));
            }
            float2 o01 = make_float2(c0, c1);
            float2 o23 = make_float2(c2, c3);
            *(float2*)&C[(size_t)r0 * ldc + col]       = o01;
            *(float2*)&C[(size_t)(r0 + 8) * ldc + col] = o23;
        }
    }
}

// ---------------------------------------------------------------------------
// Embedding + positional encoding. One block per token, 256 threads.
// ---------------------------------------------------------------------------
__global__ void embed_k(const int* __restrict__ x, const float* __restrict__ W,
                        float* __restrict__ h)
{
    const int token = blockIdx.x;
    const int t  = token & (SEQ - 1);
    const int id = x[token];
    const int tid = threadIdx.x;
    #pragma unroll
    for (int u = 0; u < 2; u++) {
        const int c = tid + u * 256;
        const int j = c >> 1;
        const float ang = (float)t * expf(-(float)j * 0.07195578415606394f);
        const float p = (c & 1) ? cosf(ang) : sinf(ang);
        h[(size_t)token * KD + c] = W[(size_t)id * KD + c] + p;
    }
}

// ---------------------------------------------------------------------------
// Causal softmax (scale folded in). grid(SEQ, B*H), 256 threads.
// ---------------------------------------------------------------------------
__global__ void softmax_k(float* __restrict__ att)
{
    const int q  = blockIdx.x;
    const int bh = blockIdx.y;
    float* row = att + ((size_t)bh * SEQ + q) * SEQ;
    const int tid = threadIdx.x;
    const float scale = 0.04419417382415922f;  // 1/sqrt(512)
    __shared__ float red[256];

    const float s0 = (tid       <= q) ? row[tid]       * scale : -3.4e38f;
    const float s1 = (tid + 256 <= q) ? row[tid + 256] * scale : -3.4e38f;
    red[tid] = fmaxf(s0, s1);
    __syncthreads();
    for (int o = 128; o; o >>= 1) {
        if (tid < o) red[tid] = fmaxf(red[tid], red[tid + o]);
        __syncthreads();
    }
    const float m = red[0];
    __syncthreads();
    const float v0 = (tid       <= q) ? expf(s0 - m) : 0.f;
    const float v1 = (tid + 256 <= q) ? expf(s1 - m) : 0.f;
    red[tid] = v0 + v1;
    __syncthreads();
    for (int o = 128; o; o >>= 1) {
        if (tid < o) red[tid] += red[tid + o];
        __syncthreads();
    }
    const float inv = 1.0f / red[0];
    row[tid]       = v0 * inv;
    row[tid + 256] = v1 * inv;
}

// ---------------------------------------------------------------------------
// (optional residual) + LayerNorm. One block per token, 256 threads.
// ---------------------------------------------------------------------------
__global__ void ln_k(const float* __restrict__ src, float* __restrict__ h,
                     const float* __restrict__ w, const float* __restrict__ b,
                     int residual)
{
    const int token = blockIdx.x;
    const size_t base = (size_t)token * KD;
    const int tid = threadIdx.x;
    float x0 = src[base + tid];
    float x1 = src[base + tid + 256];
    if (residual) { x0 += h[base + tid]; x1 += h[base + tid + 256]; }
    __shared__ float s1[256], s2[256];
    s1[tid] = x0 + x1;
    s2[tid] = x0 * x0 + x1 * x1;
    __syncthreads();
    for (int o = 128; o; o >>= 1) {
        if (tid < o) { s1[tid] += s1[tid + o]; s2[tid] += s2[tid + o]; }
        __syncthreads();
    }
    const float mean = s1[0] * (1.f / KD);
    const float var  = s2[0] * (1.f / KD) - mean * mean;
    const float r = rsqrtf(var + 1e-5f);
    h[base + tid]       = (x0 - mean) * r * w[tid]       + b[tid];
    h[base + tid + 256] = (x1 - mean) * r * w[tid + 256] + b[tid + 256];
}

// ---------------------------------------------------------------------------
// Host-side launcher
// ---------------------------------------------------------------------------
static inline void run_gemm(int transb, int epi,
                            const float* A, const float* B, const float* bias, float* C,
                            int M, int N, int K, int lda, int ldb, int ldc,
                            long aO, long aI, long bO, long bI, long cO, long cI,
                            int zdiv, int batches)
{
    dim3 grid(N / 128, M / 128, batches), block(256);
    if (transb) {
        gemm_tc<1, 0><<<grid, block>>>(A, B, bias, C, M, N, K, lda, ldb, ldc,
                                       aO, aI, bO, bI, cO, cI, zdiv);
    } else if (epi == 0) {
        gemm_tc<0, 0><<<grid, block>>>(A, B, bias, C, M, N, K, lda, ldb, ldc,
                                       aO, aI, bO, bI, cO, cI, zdiv);
    } else if (epi == 1) {
        gemm_tc<0, 1><<<grid, block>>>(A, B, bias, C, M, N, K, lda, ldb, ldc,
                                       aO, aI, bO, bI, cO, cI, zdiv);
    } else {
        gemm_tc<0, 2><<<grid, block>>>(A, B, bias, C, M, N, K, lda, ldb, ldc,
                                       aO, aI, bO, bI, cO, cI, zdiv);
    }
}

extern "C" void kernel_launch(void* const* d_in, const int* in_sizes, int n_in,
                              void* d_out, int out_size)
{
    const int*   x        = (const int*)  d_in[0];
    const float* embed_W  = (const float*)d_in[1];
    const float* Wq       = (const float*)d_in[2];
    const float* Wk       = (const float*)d_in[3];
    const float* Wv       = (const float*)d_in[4];
    const float* Wu       = (const float*)d_in[5];
    const float* bu       = (const float*)d_in[6];
    const float* W1       = (const float*)d_in[7];
    const float* b1       = (const float*)d_in[8];
    const float* W2       = (const float*)d_in[9];
    const float* b2       = (const float*)d_in[10];
    const float* ln1_w    = (const float*)d_in[11];
    const float* ln1_b    = (const float*)d_in[12];
    const float* ln2_w    = (const float*)d_in[13];
    const float* ln2_b    = (const float*)d_in[14];
    const float* lnf_w    = (const float*)d_in[15];
    const float* lnf_b    = (const float*)d_in[16];
    const float* unembedW = (const float*)d_in[17];
    const float* unembedB = (const float*)d_in[18];
    float* out = (float*)d_out;

    float *h, *q, *k, *v, *att, *y, *tmp, *ff;
    cudaGetSymbolAddress((void**)&h,   g_h);
    cudaGetSymbolAddress((void**)&q,   g_q);
    cudaGetSymbolAddress((void**)&k,   g_k);
    cudaGetSymbolAddress((void**)&v,   g_v);
    cudaGetSymbolAddress((void**)&att, g_att);
    cudaGetSymbolAddress((void**)&y,   g_y);
    cudaGetSymbolAddress((void**)&tmp, g_tmp);
    cudaGetSymbolAddress((void**)&ff,  g_ff);

    embed_k<<<MTOK, 256>>>(x, embed_W, h);

    const long bhO = (long)SEQ * HK;           // batch stride in q/k/v/y
    const long hdI = (long)KD;                 // head stride within a row
    const long atO = (long)HEADS * SEQ * SEQ;  // att batch stride
    const long atI = (long)SEQ * SEQ;          // att head stride

    for (int i = 0; i < NBLK; i++) {
        const float* Wq_i = Wq + (size_t)i * KD * HK;
        const float* Wk_i = Wk + (size_t)i * KD * HK;
        const float* Wv_i = Wv + (size_t)i * KD * HK;
        const float* Wu_i = Wu + (size_t)i * HK * KD;
        const float* bu_i = bu + (size_t)i * KD;
        const float* W1_i = W1 + (size_t)i * KD * FF;
        const float* b1_i = b1 + (size_t)i * FF;
        const float* W2_i = W2 + (size_t)i * FF * KD;
        const float* b2_i = b2 + (size_t)i * KD;

        run_gemm(0, 0, h, Wq_i, nullptr, q, MTOK, HK, KD, KD, HK, HK,
                 0, 0, 0, 0, 0, 0, 1, 1);
        run_gemm(0, 0, h, Wk_i, nullptr, k, MTOK, HK, KD, KD, HK, HK,
                 0, 0, 0, 0, 0, 0, 1, 1);
        run_gemm(0, 0, h, Wv_i, nullptr, v, MTOK, HK, KD, KD, HK, HK,
                 0, 0, 0, 0, 0, 0, 1, 1);

        // scores = Q @ K^T (batched over b*h = 32)
        run_gemm(1, 0, q, k, nullptr, att, SEQ, SEQ, KD, HK, HK, SEQ,
                 bhO, hdI, bhO, hdI, atO, atI, HEADS, BATCH * HEADS);

        softmax_k<<<dim3(SEQ, BATCH * HEADS), 256>>>(att);

        // y = att @ V (batched)
        run_gemm(0, 0, att, v, nullptr, y, SEQ, SEQ, SEQ, SEQ, HK, HK,
                 (long)HEADS * atI, atI, bhO, hdI, bhO, hdI, HEADS, BATCH * HEADS);

        run_gemm(0, 1, y, Wu_i, bu_i, tmp, MTOK, KD, HK, HK, KD, KD,
                 0, 0, 0, 0, 0, 0, 1, 1);

        ln_k<<<MTOK, 256>>>(tmp, h, ln1_w + (size_t)i * KD, ln1_b + (size_t)i * KD, 1);

        run_gemm(0, 2, h, W1_i, b1_i, ff, MTOK, FF, KD, KD, FF, FF,
                 0, 0, 0, 0, 0, 0, 1, 1);

        run_gemm(0, 1, ff, W2_i, b2_i, tmp, MTOK, KD, FF, FF, KD, KD,
                 0, 0, 0, 0, 0, 0, 1, 1);

        ln_k<<<MTOK, 256>>>(tmp, h, ln2_w + (size_t)i * KD, ln2_b + (size_t)i * KD, 1);
    }

    ln_k<<<MTOK, 256>>>(h, h, lnf_w, lnf_b, 0);

    run_gemm(0, 1, h, unembedW, unembedB, out, MTOK, VOCAB, KD, KD, VOCAB, VOCAB,
             0, 0, 0, 0, 0, 0, 1, 1);
}

// round 4
// speedup vs baseline: 2.0000x; 1.7410x over previous
#include <cuda_runtime.h>
#include <cuda_bf16.h>
#include <math.h>

// ---------------------------------------------------------------------------
// GPT forward. bf16x3 split-precision tensor-core GEMMs, fp32 elementwise.
// B=4, T=512, K=512, H=8, NB=4, VOCAB=32000. M = B*T = 2048 tokens.
// ---------------------------------------------------------------------------

#define BATCH 4
#define SEQ   512
#define KD    512
#define HEADS 8
#define NBLK  4
#define VOCAB 32000
#define MTOK  (BATCH*SEQ)        // 2048
#define HK    (HEADS*KD)         // 4096
#define FF    (4*KD)             // 2048

// Scratch (device globals; no allocation allowed)
__device__ float g_h  [MTOK*KD];
__device__ float g_q  [MTOK*HK];
__device__ float g_k  [MTOK*HK];
__device__ float g_v  [MTOK*HK];
__device__ float g_att[BATCH*HEADS*SEQ*SEQ];
__device__ float g_y  [MTOK*HK];
__device__ float g_tmp[MTOK*KD];
__device__ float g_ff [MTOK*FF];

// ---------------------------------------------------------------------------
// helpers
// ---------------------------------------------------------------------------
__device__ __forceinline__ void split_pair(float x0, float x1,
                                           unsigned& hi, unsigned& lo) {
    __nv_bfloat16 h0 = __float2bfloat16(x0);
    __nv_bfloat16 h1 = __float2bfloat16(x1);
    float r0 = x0 - __bfloat162float(h0);
    float r1 = x1 - __bfloat162float(h1);
    __nv_bfloat162 H = __halves2bfloat162(h0, h1);
    __nv_bfloat162 L = __halves2bfloat162(__float2bfloat16(r0), __float2bfloat16(r1));
    hi = *reinterpret_cast<unsigned*>(&H);
    lo = *reinterpret_cast<unsigned*>(&L);
}

__device__ __forceinline__ void mma16(float* c, const unsigned* a, const unsigned* b) {
    asm volatile(
        "mma.sync.aligned.m16n8k16.row.col.f32.bf16.bf16.f32 "
        "{%0,%1,%2,%3},{%4,%5,%6,%7},{%8,%9},{%0,%1,%2,%3};"
        : "+f"(c[0]), "+f"(c[1]), "+f"(c[2]), "+f"(c[3])
        : "r"(a[0]), "r"(a[1]), "r"(a[2]), "r"(a[3]), "r"(b[0]), "r"(b[1]));
}

// SMEM layout: uint32 sm[2 bufs][4 regions][16 kp][128 col], 64KB dynamic.
// Region order: AH=0, AL=1, BH=2, BL=3.
#define SM_BUF   8192
#define SM_AH    0
#define SM_AL    2048
#define SM_BH    4096
#define SM_BL    6144
// swizzled column
__device__ __forceinline__ int swz(int kp, int c) {
    return c ^ ((kp & 3) << 3) ^ ((kp >> 3) << 4);
}

// Store a 128(row)x32(k) fp32 chunk held as 16 consecutive k-values per thread
// (rows ar, k-half akh) into split bf16 pair-packed SMEM.
__device__ __forceinline__ void store_rowmajor(unsigned* dstH, unsigned* dstL,
                                               const float4* r, int ar, int akh) {
    const float* f = (const float*)r;
    #pragma unroll
    for (int p = 0; p < 8; p++) {
        unsigned hi, lo;
        split_pair(f[2 * p], f[2 * p + 1], hi, lo);
        const int kp  = 8 * akh + p;
        const int col = ar ^ ((p & 3) << 3) ^ (akh << 4);
        dstH[kp * 128 + col] = hi;
        dstL[kp * 128 + col] = lo;
    }
}

// Store B (NN, [K,N]) chunk: thread holds rows {2kb,2kb+1,2kb+16,2kb+17} x 4 n.
__device__ __forceinline__ void store_bnn(unsigned* dstH, unsigned* dstL,
                                          const float4* r, int kb, int n0) {
    #pragma unroll
    for (int pass = 0; pass < 2; pass++) {
        const int kp = kb + 8 * pass;
        const float* e = (const float*)(r + 2 * pass);
        const float* o = (const float*)(r + 2 * pass + 1);
        unsigned hi[4], lo[4];
        #pragma unroll
        for (int j = 0; j < 4; j++) split_pair(e[j], o[j], hi[j], lo[j]);
        const int col = n0 ^ ((kp & 3) << 3) ^ ((kp >> 3) << 4);
        *(uint4*)&dstH[kp * 128 + col] = make_uint4(hi[0], hi[1], hi[2], hi[3]);
        *(uint4*)&dstL[kp * 128 + col] = make_uint4(lo[0], lo[1], lo[2], lo[3]);
    }
}

// ---------------------------------------------------------------------------
// bf16x3 tensor-core GEMM: C = A(MxK) * op(B) (+bias)(+gelu)
//  TRANSB=0: B is [K,N] row-major. TRANSB=1: B is [N,K] row-major.
//  EPI: 0 none, 1 +bias, 2 gelu(x+bias)
// Tile 128x128x32, 256 threads (8 warps 2x4), warp tile 64x32, double-buffered.
// Requires M%128==0, N%128==0, K%32==0.
// ---------------------------------------------------------------------------
template<int TRANSB, int EPI>
__global__ __launch_bounds__(256, 1)
void gemm_bf3(const float* __restrict__ A, const float* __restrict__ B,
              const float* __restrict__ bias, float* __restrict__ C,
              int M, int N, int K, int lda, int ldb, int ldc,
              long aO, long aI, long bO, long bI, long cO, long cI, int zdiv)
{
    extern __shared__ unsigned sm[];

    const int z  = blockIdx.z;
    const int zb = z / zdiv, zh = z - zb * zdiv;
    A += (size_t)zb * aO + (size_t)zh * aI;
    B += (size_t)zb * bO + (size_t)zh * bI;
    C += (size_t)zb * cO + (size_t)zh * cI;

    const int tid  = threadIdx.x;
    const int lane = tid & 31;
    const int warp = tid >> 5;
    const int g    = lane >> 2;
    const int tc   = lane & 3;
    const int wm   = (warp >> 2) * 64;
    const int wn   = (warp & 3) * 32;
    const int bx   = blockIdx.x, by = blockIdx.y;

    // A staging map: row ar, k-half akh (16 k each)
    const int ar  = tid >> 1;
    const int akh = tid & 1;
    const float* Aptr = A + (size_t)(by * 128 + ar) * lda + 16 * akh;

    // B staging map
    const float* Bptr = nullptr;   // TRANSB (rows = n)
    const float* Bnn  = nullptr;   // NN
    int kb = 0, n0 = 0;
    if (TRANSB) {
        Bptr = B + (size_t)(bx * 128 + ar) * ldb + 16 * akh;
    } else {
        kb  = tid >> 5;            // 0..7
        n0  = (lane) * 4;          // 0..124
        Bnn = B + bx * 128 + n0;
    }

    float acc[4][4][4];
    #pragma unroll
    for (int i = 0; i < 4; i++)
        #pragma unroll
        for (int j = 0; j < 4; j++)
            #pragma unroll
            for (int r = 0; r < 4; r++) acc[i][j][r] = 0.f;

    float4 aR[4], bR[4];

    // ---- chunk loaders into registers ----
    auto LOADA = [&](int k0) {
        #pragma unroll
        for (int i = 0; i < 4; i++)
            aR[i] = *(const float4*)(Aptr + k0 + 4 * i);
    };
    auto LOADB = [&](int k0) {
        if (TRANSB) {
            #pragma unroll
            for (int i = 0; i < 4; i++)
                bR[i] = *(const float4*)(Bptr + k0 + 4 * i);
        } else {
            bR[0] = *(const float4*)(Bnn + (size_t)(k0 + 2 * kb)      * ldb);
            bR[1] = *(const float4*)(Bnn + (size_t)(k0 + 2 * kb + 1)  * ldb);
            bR[2] = *(const float4*)(Bnn + (size_t)(k0 + 2 * kb + 16) * ldb);
            bR[3] = *(const float4*)(Bnn + (size_t)(k0 + 2 * kb + 17) * ldb);
        }
    };
    auto STORE = [&](int buf) {
        unsigned* base = sm + buf * SM_BUF;
        store_rowmajor(base + SM_AH, base + SM_AL, aR, ar, akh);
        if (TRANSB) store_rowmajor(base + SM_BH, base + SM_BL, bR, ar, akh);
        else        store_bnn     (base + SM_BH, base + SM_BL, bR, kb, n0);
    };

    const int nc = K >> 5;   // chunks of 32

    LOADA(0); LOADB(0);
    STORE(0);
    if (nc > 1) { LOADA(32); LOADB(32); }
    __syncthreads();

    for (int i = 0; i < nc; i++) {
        if (i + 1 < nc) STORE((i + 1) & 1);
        if (i + 2 < nc) { LOADA(32 * (i + 2)); LOADB(32 * (i + 2)); }

        const unsigned* base = sm + (i & 1) * SM_BUF;
        #pragma unroll
        for (int kpb = 0; kpb <= 8; kpb += 8) {
            const int xb = (kpb >> 3) << 4;
            unsigned Ah[4][4], Al[4][4], Bh[4][2], Bl[4][2];
            #pragma unroll
            for (int mf = 0; mf < 4; mf++) {
                const int m  = wm + mf * 16 + g;
                const int c0 = (m)     ^ (tc << 3) ^ xb;
                const int c1 = (m + 8) ^ (tc << 3) ^ xb;
                const int r0 = (kpb + tc) * 128;
                const int r1 = (kpb + 4 + tc) * 128;
                Ah[mf][0] = base[SM_AH + r0 + c0];
                Ah[mf][1] = base[SM_AH + r0 + c1];
                Ah[mf][2] = base[SM_AH + r1 + c0];
                Ah[mf][3] = base[SM_AH + r1 + c1];
                Al[mf][0] = base[SM_AL + r0 + c0];
                Al[mf][1] = base[SM_AL + r0 + c1];
                Al[mf][2] = base[SM_AL + r1 + c0];
                Al[mf][3] = base[SM_AL + r1 + c1];
            }
            #pragma unroll
            for (int nf = 0; nf < 4; nf++) {
                const int n  = wn + nf * 8 + g;
                const int c  = n ^ (tc << 3) ^ xb;
                const int r0 = (kpb + tc) * 128;
                const int r1 = (kpb + 4 + tc) * 128;
                Bh[nf][0] = base[SM_BH + r0 + c];
                Bh[nf][1] = base[SM_BH + r1 + c];
                Bl[nf][0] = base[SM_BL + r0 + c];
                Bl[nf][1] = base[SM_BL + r1 + c];
            }
            #pragma unroll
            for (int mf = 0; mf < 4; mf++)
                #pragma unroll
                for (int nf = 0; nf < 4; nf++) {
                    mma16(acc[mf][nf], Ah[mf], Bl[nf]);
                    mma16(acc[mf][nf], Al[mf], Bh[nf]);
                    mma16(acc[mf][nf], Ah[mf], Bh[nf]);
                }
        }
        __syncthreads();
    }

    // ---- epilogue ----
    #pragma unroll
    for (int mf = 0; mf < 4; mf++) {
        const int r0 = by * 128 + wm + mf * 16 + g;
        #pragma unroll
        for (int nf = 0; nf < 4; nf++) {
            const int col = bx * 128 + wn + nf * 8 + tc * 2;
            float c0 = acc[mf][nf][0], c1 = acc[mf][nf][1];
            float c2 = acc[mf][nf][2], c3 = acc[mf][nf][3];
            if (EPI >= 1) {
                const float b0v = bias[col], b1v = bias[col + 1];
                c0 += b0v; c1 += b1v; c2 += b0v; c3 += b1v;
            }
            if (EPI == 2) {
                c0 = 0.5f * c0 * (1.0f + erff(c0 * 0.7071067811865475f));
                c1 = 0.5f * c1 * (1.0f + erff(c1 * 0.7071067811865475f));
                c2 = 0.5f * c2 * (1.0f + erff(c2 * 0.7071067811865475f));
                c3 = 0.5f * c3 * (1.0f + erff(c3 * 0.7071067811865475f));
            }
            *(float2*)&C[(size_t)r0 * ldc + col]       = make_float2(c0, c1);
            *(float2*)&C[(size_t)(r0 + 8) * ldc + col] = make_float2(c2, c3);
        }
    }
}

// ---------------------------------------------------------------------------
// Embedding + positional encoding. One block per token, 256 threads.
// ---------------------------------------------------------------------------
__global__ void embed_k(const int* __restrict__ x, const float* __restrict__ W,
                        float* __restrict__ h)
{
    const int token = blockIdx.x;
    const int t  = token & (SEQ - 1);
    const int id = x[token];
    const int tid = threadIdx.x;
    #pragma unroll
    for (int u = 0; u < 2; u++) {
        const int c = tid + u * 256;
        const int j = c >> 1;
        const float ang = (float)t * expf(-(float)j * 0.07195578415606394f);
        const float p = (c & 1) ? cosf(ang) : sinf(ang);
        h[(size_t)token * KD + c] = W[(size_t)id * KD + c] + p;
    }
}

// ---------------------------------------------------------------------------
// Causal softmax (scale folded in). grid(SEQ, B*H), 256 threads.
// ---------------------------------------------------------------------------
__global__ void softmax_k(float* __restrict__ att)
{
    const int q  = blockIdx.x;
    const int bh = blockIdx.y;
    float* row = att + ((size_t)bh * SEQ + q) * SEQ;
    const int tid = threadIdx.x;
    const float scale = 0.04419417382415922f;  // 1/sqrt(512)
    __shared__ float red[256];

    const float s0 = (tid       <= q) ? row[tid]       * scale : -3.4e38f;
    const float s1 = (tid + 256 <= q) ? row[tid + 256] * scale : -3.4e38f;
    red[tid] = fmaxf(s0, s1);
    __syncthreads();
    for (int o = 128; o; o >>= 1) {
        if (tid < o) red[tid] = fmaxf(red[tid], red[tid + o]);
        __syncthreads();
    }
    const float m = red[0];
    __syncthreads();
    const float v0 = (tid       <= q) ? expf(s0 - m) : 0.f;
    const float v1 = (tid + 256 <= q) ? expf(s1 - m) : 0.f;
    red[tid] = v0 + v1;
    __syncthreads();
    for (int o = 128; o; o >>= 1) {
        if (tid < o) red[tid] += red[tid + o];
        __syncthreads();
    }
    const float inv = 1.0f / red[0];
    row[tid]       = v0 * inv;
    row[tid + 256] = v1 * inv;
}

// ---------------------------------------------------------------------------
// (optional residual) + LayerNorm. One block per token, 256 threads.
// ---------------------------------------------------------------------------
__global__ void ln_k(const float* __restrict__ src, float* __restrict__ h,
                     const float* __restrict__ w, const float* __restrict__ b,
                     int residual)
{
    const int token = blockIdx.x;
    const size_t base = (size_t)token * KD;
    const int tid = threadIdx.x;
    float x0 = src[base + tid];
    float x1 = src[base + tid + 256];
    if (residual) { x0 += h[base + tid]; x1 += h[base + tid + 256]; }
    __shared__ float s1[256], s2[256];
    s1[tid] = x0 + x1;
    s2[tid] = x0 * x0 + x1 * x1;
    __syncthreads();
    for (int o = 128; o; o >>= 1) {
        if (tid < o) { s1[tid] += s1[tid + o]; s2[tid] += s2[tid + o]; }
        __syncthreads();
    }
    const float mean = s1[0] * (1.f / KD);
    const float var  = s2[0] * (1.f / KD) - mean * mean;
    const float r = rsqrtf(var + 1e-5f);
    h[base + tid]       = (x0 - mean) * r * w[tid]       + b[tid];
    h[base + tid + 256] = (x1 - mean) * r * w[tid + 256] + b[tid + 256];
}

// ---------------------------------------------------------------------------
// Host-side launcher
// ---------------------------------------------------------------------------
#define GEMM_SMEM 65536

static inline void run_gemm(int transb, int epi,
                            const float* A, const float* B, const float* bias, float* C,
                            int M, int N, int K, int lda, int ldb, int ldc,
                            long aO, long aI, long bO, long bI, long cO, long cI,
                            int zdiv, int batches)
{
    dim3 grid(N / 128, M / 128, batches), block(256);
    if (transb) {
        cudaFuncSetAttribute(gemm_bf3<1, 0>, cudaFuncAttributeMaxDynamicSharedMemorySize, GEMM_SMEM);
        gemm_bf3<1, 0><<<grid, block, GEMM_SMEM>>>(A, B, bias, C, M, N, K, lda, ldb, ldc,
                                                   aO, aI, bO, bI, cO, cI, zdiv);
    } else if (epi == 0) {
        cudaFuncSetAttribute(gemm_bf3<0, 0>, cudaFuncAttributeMaxDynamicSharedMemorySize, GEMM_SMEM);
        gemm_bf3<0, 0><<<grid, block, GEMM_SMEM>>>(A, B, bias, C, M, N, K, lda, ldb, ldc,
                                                   aO, aI, bO, bI, cO, cI, zdiv);
    } else if (epi == 1) {
        cudaFuncSetAttribute(gemm_bf3<0, 1>, cudaFuncAttributeMaxDynamicSharedMemorySize, GEMM_SMEM);
        gemm_bf3<0, 1><<<grid, block, GEMM_SMEM>>>(A, B, bias, C, M, N, K, lda, ldb, ldc,
                                                   aO, aI, bO, bI, cO, cI, zdiv);
    } else {
        cudaFuncSetAttribute(gemm_bf3<0, 2>, cudaFuncAttributeMaxDynamicSharedMemorySize, GEMM_SMEM);
        gemm_bf3<0, 2><<<grid, block, GEMM_SMEM>>>(A, B, bias, C, M, N, K, lda, ldb, ldc,
                                                   aO, aI, bO, bI, cO, cI, zdiv);
    }
}

extern "C" void kernel_launch(void* const* d_in, const int* in_sizes, int n_in,
                              void* d_out, int out_size)
{
    const int*   x        = (const int*)  d_in[0];
    const float* embed_W  = (const float*)d_in[1];
    const float* Wq       = (const float*)d_in[2];
    const float* Wk       = (const float*)d_in[3];
    const float* Wv       = (const float*)d_in[4];
    const float* Wu       = (const float*)d_in[5];
    const float* bu       = (const float*)d_in[6];
    const float* W1       = (const float*)d_in[7];
    const float* b1       = (const float*)d_in[8];
    const float* W2       = (const float*)d_in[9];
    const float* b2       = (const float*)d_in[10];
    const float* ln1_w    = (const float*)d_in[11];
    const float* ln1_b    = (const float*)d_in[12];
    const float* ln2_w    = (const float*)d_in[13];
    const float* ln2_b    = (const float*)d_in[14];
    const float* lnf_w    = (const float*)d_in[15];
    const float* lnf_b    = (const float*)d_in[16];
    const float* unembedW = (const float*)d_in[17];
    const float* unembedB = (const float*)d_in[18];
    float* out = (float*)d_out;

    float *h, *q, *k, *v, *att, *y, *tmp, *ff;
    cudaGetSymbolAddress((void**)&h,   g_h);
    cudaGetSymbolAddress((void**)&q,   g_q);
    cudaGetSymbolAddress((void**)&k,   g_k);
    cudaGetSymbolAddress((void**)&v,   g_v);
    cudaGetSymbolAddress((void**)&att, g_att);
    cudaGetSymbolAddress((void**)&y,   g_y);
    cudaGetSymbolAddress((void**)&tmp, g_tmp);
    cudaGetSymbolAddress((void**)&ff,  g_ff);

    embed_k<<<MTOK, 256>>>(x, embed_W, h);

    const long bhO = (long)SEQ * HK;           // batch stride in q/k/v/y
    const long hdI = (long)KD;                 // head stride within a row
    const long atO = (long)HEADS * SEQ * SEQ;  // att batch stride
    const long atI = (long)SEQ * SEQ;          // att head stride

    for (int i = 0; i < NBLK; i++) {
        const float* Wq_i = Wq + (size_t)i * KD * HK;
        const float* Wk_i = Wk + (size_t)i * KD * HK;
        const float* Wv_i = Wv + (size_t)i * KD * HK;
        const float* Wu_i = Wu + (size_t)i * HK * KD;
        const float* bu_i = bu + (size_t)i * KD;
        const float* W1_i = W1 + (size_t)i * KD * FF;
        const float* b1_i = b1 + (size_t)i * FF;
        const float* W2_i = W2 + (size_t)i * FF * KD;
        const float* b2_i = b2 + (size_t)i * KD;

        run_gemm(0, 0, h, Wq_i, nullptr, q, MTOK, HK, KD, KD, HK, HK,
                 0, 0, 0, 0, 0, 0, 1, 1);
        run_gemm(0, 0, h, Wk_i, nullptr, k, MTOK, HK, KD, KD, HK, HK,
                 0, 0, 0, 0, 0, 0, 1, 1);
        run_gemm(0, 0, h, Wv_i, nullptr, v, MTOK, HK, KD, KD, HK, HK,
                 0, 0, 0, 0, 0, 0, 1, 1);

        // scores = Q @ K^T (batched over b*h = 32)
        run_gemm(1, 0, q, k, nullptr, att, SEQ, SEQ, KD, HK, HK, SEQ,
                 bhO, hdI, bhO, hdI, atO, atI, HEADS, BATCH * HEADS);

        softmax_k<<<dim3(SEQ, BATCH * HEADS), 256>>>(att);

        // y = att @ V (batched)
        run_gemm(0, 0, att, v, nullptr, y, SEQ, SEQ, SEQ, SEQ, HK, HK,
                 (long)HEADS * atI, atI, bhO, hdI, bhO, hdI, HEADS, BATCH * HEADS);

        run_gemm(0, 1, y, Wu_i, bu_i, tmp, MTOK, KD, HK, HK, KD, KD,
                 0, 0, 0, 0, 0, 0, 1, 1);

        ln_k<<<MTOK, 256>>>(tmp, h, ln1_w + (size_t)i * KD, ln1_b + (size_t)i * KD, 1);

        run_gemm(0, 2, h, W1_i, b1_i, ff, MTOK, FF, KD, KD, FF, FF,
                 0, 0, 0, 0, 0, 0, 1, 1);

        run_gemm(0, 1, ff, W2_i, b2_i, tmp, MTOK, KD, FF, FF, KD, KD,
                 0, 0, 0, 0, 0, 0, 1, 1);

        ln_k<<<MTOK, 256>>>(tmp, h, ln2_w + (size_t)i * KD, ln2_b + (size_t)i * KD, 1);
    }

    ln_k<<<MTOK, 256>>>(h, h, lnf_w, lnf_b, 0);

    run_gemm(0, 1, h, unembedW, unembedB, out, MTOK, VOCAB, KD, KD, VOCAB, VOCAB,
             0, 0, 0, 0, 0, 0, 1, 1);
}

// round 5
// speedup vs baseline: 2.2693x; 1.1347x over previous
#include <cuda_runtime.h>
#include <cuda_bf16.h>
#include <math.h>

// ---------------------------------------------------------------------------
// GPT forward. Pre-split bf16x3 tensor-core GEMMs with cp.async pipeline.
// B=4, T=512, K=512, H=8, NB=4, VOCAB=32000. M = B*T = 2048 tokens.
//
// All GEMM operands are pre-split packed bf16 (hi = bf16(x), lo = bf16(x-hi)),
// both A and B stored k-contiguous. GEMM = cp.async 4-stage pipeline +
// ldmatrix + 3x mma.m16n8k16.bf16 (Ah*Bh + Ah*Bl + Al*Bh).
// ---------------------------------------------------------------------------

#define BATCH 4
#define SEQ   512
#define KD    512
#define HEADS 8
#define NBLK  4
#define VOCAB 32000
#define MTOK  (BATCH*SEQ)        // 2048
#define HK    (HEADS*KD)         // 4096
#define FF    (4*KD)             // 2048
#define NBH   (BATCH*HEADS)      // 32

// fp32 scratch
__device__ float g_h  [MTOK*KD];
__device__ float g_v  [MTOK*HK];
__device__ float g_att[NBH*SEQ*SEQ];
__device__ float g_tmp[MTOK*KD];
// split bf16 scratch
__device__ __nv_bfloat16 g_hs_h[MTOK*KD],  g_hs_l[MTOK*KD];
__device__ __nv_bfloat16 g_wt_h[(size_t)VOCAB*KD], g_wt_l[(size_t)VOCAB*KD];
__device__ __nv_bfloat16 g_qs_h[MTOK*HK],  g_qs_l[MTOK*HK];
__device__ __nv_bfloat16 g_ks_h[MTOK*HK],  g_ks_l[MTOK*HK];
__device__ __nv_bfloat16 g_vt_h[MTOK*HK],  g_vt_l[MTOK*HK];
__device__ __nv_bfloat16 g_as_h[NBH*SEQ*SEQ], g_as_l[NBH*SEQ*SEQ];
__device__ __nv_bfloat16 g_ys_h[MTOK*HK],  g_ys_l[MTOK*HK];
__device__ __nv_bfloat16 g_fs_h[MTOK*FF],  g_fs_l[MTOK*FF];

// ---------------------------------------------------------------------------
// helpers
// ---------------------------------------------------------------------------
__device__ __forceinline__ unsigned smem_u32(const void* p) {
    unsigned r;
    asm("{ .reg .u64 t; cvta.to.shared.u64 t, %1; cvt.u32.u64 %0, t; }"
        : "=r"(r) : "l"(p));
    return r;
}
__device__ __forceinline__ void cp16(unsigned dst, const void* src) {
    asm volatile("cp.async.cg.shared.global [%0], [%1], 16;" :: "r"(dst), "l"(src));
}
#define CP_COMMIT() asm volatile("cp.async.commit_group;")
#define CP_WAIT2()  asm volatile("cp.async.wait_group 2;")

__device__ __forceinline__ void ldsm4(unsigned addr, unsigned& r0, unsigned& r1,
                                      unsigned& r2, unsigned& r3) {
    asm volatile("ldmatrix.sync.aligned.m8n8.x4.shared.b16 {%0,%1,%2,%3}, [%4];"
                 : "=r"(r0), "=r"(r1), "=r"(r2), "=r"(r3) : "r"(addr));
}
__device__ __forceinline__ void ldsm2(unsigned addr, unsigned& r0, unsigned& r1) {
    asm volatile("ldmatrix.sync.aligned.m8n8.x2.shared.b16 {%0,%1}, [%2];"
                 : "=r"(r0), "=r"(r1) : "r"(addr));
}
__device__ __forceinline__ void mma16(float* c, const unsigned* a, const unsigned* b) {
    asm volatile(
        "mma.sync.aligned.m16n8k16.row.col.f32.bf16.bf16.f32 "
        "{%0,%1,%2,%3},{%4,%5,%6,%7},{%8,%9},{%0,%1,%2,%3};"
        : "+f"(c[0]), "+f"(c[1]), "+f"(c[2]), "+f"(c[3])
        : "r"(a[0]), "r"(a[1]), "r"(a[2]), "r"(a[3]), "r"(b[0]), "r"(b[1]));
}
__device__ __forceinline__ void splitw(float v, __nv_bfloat16* ph, __nv_bfloat16* pl) {
    __nv_bfloat16 hi = __float2bfloat16(v);
    *ph = hi;
    *pl = __float2bfloat16(v - __bfloat162float(hi));
}
__device__ __forceinline__ void split2(float a, float b,
                                       __nv_bfloat162& H, __nv_bfloat162& L) {
    __nv_bfloat16 ha = __float2bfloat16(a), hb = __float2bfloat16(b);
    H = __halves2bfloat162(ha, hb);
    L = __halves2bfloat162(__float2bfloat16(a - __bfloat162float(ha)),
                           __float2bfloat16(b - __bfloat162float(hb)));
}

// SMEM stage layout (uint32 units): [AH 2048 | AL 2048 | BH 2048 | BL 2048]
// Tile row = 16 uint32 (32 bf16 along k), swizzle col' = c ^ ((row&6)<<1).
#define ST_U32 8192
#define AH_OFF 0
#define AL_OFF 2048
#define BH_OFF 4096
#define BL_OFF 6144
#define GEMM_SMEM (4*ST_U32*4)   // 131072 bytes

// ---------------------------------------------------------------------------
// Pipelined split-bf16 GEMM.
//  A (hi/lo): [M][K] bf16, lda.   B (hi/lo): [N][K] bf16, ldb.
//  C = A * B^T(logical) with epilogue:
//   EPI: 0 none, 1 +bias, 2 gelu(x+bias)
//   OUT: 0 -> fp32 C;  1 -> split bf16 Ch/Cl (same [M][N] layout)
// Batched via blockIdx.z (zdiv decomposition), strides in elements.
// Requires M%128==0, N%128==0, K%32==0, K>=96.
// ---------------------------------------------------------------------------
template<int EPI, int OUT>
__global__ __launch_bounds__(256)
void gemm_ps(const __nv_bfloat16* __restrict__ Ah, const __nv_bfloat16* __restrict__ Al,
             const __nv_bfloat16* __restrict__ Bh, const __nv_bfloat16* __restrict__ Bl,
             const float* __restrict__ bias,
             float* __restrict__ C,
             __nv_bfloat16* __restrict__ Ch, __nv_bfloat16* __restrict__ Cl,
             int M, int N, int K, int lda, int ldb, int ldc,
             long aO, long aI, long bO, long bI, long cO, long cI, int zdiv)
{
    extern __shared__ unsigned sm[];
    const unsigned base32 = smem_u32(sm);

    const int z  = blockIdx.z;
    const int zb = z / zdiv, zh = z - zb * zdiv;
    const size_t aoff = (size_t)zb * aO + (size_t)zh * aI;
    const size_t boff = (size_t)zb * bO + (size_t)zh * bI;
    const size_t coff = (size_t)zb * cO + (size_t)zh * cI;
    Ah += aoff; Al += aoff; Bh += boff; Bl += boff;

    const int tid  = threadIdx.x;
    const int lane = tid & 31;
    const int warp = tid >> 5;
    const int g    = lane >> 2;
    const int tc   = lane & 3;
    const int wm   = (warp >> 2) * 64;
    const int wn   = (warp & 3) * 32;
    const int bx   = blockIdx.x, by = blockIdx.y;

    // cp.async mapping: thread -> tile row (tid>>1), granule pair (tid&1)*2
    const int crow = tid >> 1;
    const int cj   = (tid & 1) * 2;
    const __nv_bfloat16* pAh = Ah + (size_t)(by * 128 + crow) * lda + cj * 8;
    const __nv_bfloat16* pAl = Al + (size_t)(by * 128 + crow) * lda + cj * 8;
    const __nv_bfloat16* pBh = Bh + (size_t)(bx * 128 + crow) * ldb + cj * 8;
    const __nv_bfloat16* pBl = Bl + (size_t)(bx * 128 + crow) * ldb + cj * 8;
    const int csw = (crow & 6) << 1;
    const int cs0 = crow * 16 + ((4 * cj)     ^ csw);
    const int cs1 = crow * 16 + ((4 * cj + 4) ^ csw);

    // ldmatrix source indices (uint32 units, region-relative)
    int idxA[4][2], idxB[4][2];
    {
        const int rowA = wm + (lane & 15);          // + mf*16 added below
        const int cgA0 = (lane >> 4) << 2;          // 0 or 4
        const int rowB = wn + (lane & 7);           // + nf*8 added below
        const int cgB0 = ((lane >> 3) & 1) << 2;
        #pragma unroll
        for (int mf = 0; mf < 4; mf++) {
            const int r = rowA + mf * 16;
            idxA[mf][0] = r * 16 + ((cgA0)     ^ ((r & 6) << 1));
            idxA[mf][1] = r * 16 + ((cgA0 + 8) ^ ((r & 6) << 1));
        }
        #pragma unroll
        for (int nf = 0; nf < 4; nf++) {
            const int r = rowB + nf * 8;
            idxB[nf][0] = r * 16 + ((cgB0)     ^ ((r & 6) << 1));
            idxB[nf][1] = r * 16 + ((cgB0 + 8) ^ ((r & 6) << 1));
        }
    }

    float acc[4][4][4];
    #pragma unroll
    for (int i = 0; i < 4; i++)
        #pragma unroll
        for (int j = 0; j < 4; j++)
            #pragma unroll
            for (int r = 0; r < 4; r++) acc[i][j][r] = 0.f;

    auto ISSUE = [&](int buf, int k0) {
        const unsigned sb = base32 + buf * (ST_U32 * 4);
        cp16(sb + (AH_OFF + cs0) * 4, pAh + k0);
        cp16(sb + (AH_OFF + cs1) * 4, pAh + k0 + 8);
        cp16(sb + (AL_OFF + cs0) * 4, pAl + k0);
        cp16(sb + (AL_OFF + cs1) * 4, pAl + k0 + 8);
        cp16(sb + (BH_OFF + cs0) * 4, pBh + k0);
        cp16(sb + (BH_OFF + cs1) * 4, pBh + k0 + 8);
        cp16(sb + (BL_OFF + cs0) * 4, pBl + k0);
        cp16(sb + (BL_OFF + cs1) * 4, pBl + k0 + 8);
    };

    const int nc = K >> 5;

    ISSUE(0, 0);  CP_COMMIT();
    ISSUE(1, 32); CP_COMMIT();
    ISSUE(2, 64); CP_COMMIT();

    for (int i = 0; i < nc; i++) {
        CP_WAIT2();
        __syncthreads();
        if (i + 3 < nc) ISSUE((i + 3) & 3, (i + 3) * 32);
        CP_COMMIT();

        const unsigned stb = base32 + (i & 3) * (ST_U32 * 4);
        #pragma unroll
        for (int kpb = 0; kpb < 2; kpb++) {
            unsigned Af[4][4], Lf[4][4], Bf[4][2], Mf[4][2];
            #pragma unroll
            for (int mf = 0; mf < 4; mf++) {
                ldsm4(stb + (AH_OFF + idxA[mf][kpb]) * 4,
                      Af[mf][0], Af[mf][1], Af[mf][2], Af[mf][3]);
                ldsm4(stb + (AL_OFF + idxA[mf][kpb]) * 4,
                      Lf[mf][0], Lf[mf][1], Lf[mf][2], Lf[mf][3]);
            }
            #pragma unroll
            for (int nf = 0; nf < 4; nf++) {
                ldsm2(stb + (BH_OFF + idxB[nf][kpb]) * 4, Bf[nf][0], Bf[nf][1]);
                ldsm2(stb + (BL_OFF + idxB[nf][kpb]) * 4, Mf[nf][0], Mf[nf][1]);
            }
            #pragma unroll
            for (int mf = 0; mf < 4; mf++)
                #pragma unroll
                for (int nf = 0; nf < 4; nf++) {
                    mma16(acc[mf][nf], Af[mf], Mf[nf]);
                    mma16(acc[mf][nf], Lf[mf], Bf[nf]);
                    mma16(acc[mf][nf], Af[mf], Bf[nf]);
                }
        }
        __syncthreads();
    }

    // ---- epilogue ----
    #pragma unroll
    for (int mf = 0; mf < 4; mf++) {
        const int r0 = by * 128 + wm + mf * 16 + g;
        #pragma unroll
        for (int nf = 0; nf < 4; nf++) {
            const int col = bx * 128 + wn + nf * 8 + tc * 2;
            float c0 = acc[mf][nf][0], c1 = acc[mf][nf][1];
            float c2 = acc[mf][nf][2], c3 = acc[mf][nf][3];
            if (EPI >= 1) {
                const float b0v = bias[col], b1v = bias[col + 1];
                c0 += b0v; c1 += b1v; c2 += b0v; c3 += b1v;
            }
            if (EPI == 2) {
                c0 = 0.5f * c0 * (1.0f + erff(c0 * 0.7071067811865475f));
                c1 = 0.5f * c1 * (1.0f + erff(c1 * 0.7071067811865475f));
                c2 = 0.5f * c2 * (1.0f + erff(c2 * 0.7071067811865475f));
                c3 = 0.5f * c3 * (1.0f + erff(c3 * 0.7071067811865475f));
            }
            if (OUT == 0) {
                *(float2*)&C[coff + (size_t)r0 * ldc + col]       = make_float2(c0, c1);
                *(float2*)&C[coff + (size_t)(r0 + 8) * ldc + col] = make_float2(c2, c3);
            } else {
                __nv_bfloat162 H, L;
                split2(c0, c1, H, L);
                *(__nv_bfloat162*)&Ch[coff + (size_t)r0 * ldc + col] = H;
                *(__nv_bfloat162*)&Cl[coff + (size_t)r0 * ldc + col] = L;
                split2(c2, c3, H, L);
                *(__nv_bfloat162*)&Ch[coff + (size_t)(r0 + 8) * ldc + col] = H;
                *(__nv_bfloat162*)&Cl[coff + (size_t)(r0 + 8) * ldc + col] = L;
            }
        }
    }
}

// ---------------------------------------------------------------------------
// Weight transpose + split: src fp32 [K][N] -> dst bf16 hi/lo [N][K].
// grid (K/32, N/32), block (32,8).
// ---------------------------------------------------------------------------
__global__ void wconv(const float* __restrict__ src,
                      __nv_bfloat16* __restrict__ dh, __nv_bfloat16* __restrict__ dl,
                      int K, int N)
{
    __shared__ float t[32][33];
    const int k0 = blockIdx.x * 32, n0 = blockIdx.y * 32;
    const int tx = threadIdx.x, ty = threadIdx.y;
    #pragma unroll
    for (int r = 0; r < 4; r++)
        t[ty + r * 8][tx] = src[(size_t)(k0 + ty + r * 8) * N + n0 + tx];
    __syncthreads();
    #pragma unroll
    for (int r = 0; r < 4; r++) {
        const float v = t[tx][ty + r * 8];
        const size_t o = (size_t)(n0 + ty + r * 8) * K + k0 + tx;
        splitw(v, dh + o, dl + o);
    }
}

// ---------------------------------------------------------------------------
// V transpose + split per head: v fp32 [b*t][h*d] -> vt [(b*8+h)*512+d][t].
// grid (16,16,32), block (32,8).
// ---------------------------------------------------------------------------
__global__ void vconv(const float* __restrict__ v,
                      __nv_bfloat16* __restrict__ dh, __nv_bfloat16* __restrict__ dl)
{
    __shared__ float t[32][33];
    const int z = blockIdx.z, b = z >> 3, h = z & 7;
    const int t0 = blockIdx.x * 32, d0 = blockIdx.y * 32;
    const int tx = threadIdx.x, ty = threadIdx.y;
    #pragma unroll
    for (int r = 0; r < 4; r++)
        t[ty + r * 8][tx] = v[(size_t)(b * SEQ + t0 + ty + r * 8) * HK + h * KD + d0 + tx];
    __syncthreads();
    #pragma unroll
    for (int r = 0; r < 4; r++) {
        const float val = t[tx][ty + r * 8];
        const size_t o = ((size_t)z * KD + d0 + ty + r * 8) * SEQ + t0 + tx;
        splitw(val, dh + o, dl + o);
    }
}

// ---------------------------------------------------------------------------
// Embedding + positional encoding (+ split). One block per token.
// ---------------------------------------------------------------------------
__global__ void embed_k(const int* __restrict__ x, const float* __restrict__ W,
                        float* __restrict__ h,
                        __nv_bfloat16* __restrict__ hh, __nv_bfloat16* __restrict__ hl)
{
    const int token = blockIdx.x;
    const int t  = token & (SEQ - 1);
    const int id = x[token];
    const int tid = threadIdx.x;
    #pragma unroll
    for (int u = 0; u < 2; u++) {
        const int c = tid + u * 256;
        const int j = c >> 1;
        const float ang = (float)t * expf(-(float)j * 0.07195578415606394f);
        const float p = (c & 1) ? cosf(ang) : sinf(ang);
        const float val = W[(size_t)id * KD + c] + p;
        const size_t o = (size_t)token * KD + c;
        h[o] = val;
        splitw(val, hh + o, hl + o);
    }
}

// ---------------------------------------------------------------------------
// Causal softmax (scale folded), writes split bf16. grid(SEQ, 32), 256 thr.
// ---------------------------------------------------------------------------
__global__ void softmax_k(const float* __restrict__ att,
                          __nv_bfloat16* __restrict__ oh, __nv_bfloat16* __restrict__ ol)
{
    const int q  = blockIdx.x;
    const int bh = blockIdx.y;
    const size_t base = ((size_t)bh * SEQ + q) * SEQ;
    const int tid = threadIdx.x;
    const float scale = 0.04419417382415922f;  // 1/sqrt(512)
    __shared__ float red[256];

    const float s0 = (tid       <= q) ? att[base + tid]       * scale : -3.4e38f;
    const float s1 = (tid + 256 <= q) ? att[base + tid + 256] * scale : -3.4e38f;
    red[tid] = fmaxf(s0, s1);
    __syncthreads();
    for (int o = 128; o; o >>= 1) {
        if (tid < o) red[tid] = fmaxf(red[tid], red[tid + o]);
        __syncthreads();
    }
    const float m = red[0];
    __syncthreads();
    const float v0 = (tid       <= q) ? expf(s0 - m) : 0.f;
    const float v1 = (tid + 256 <= q) ? expf(s1 - m) : 0.f;
    red[tid] = v0 + v1;
    __syncthreads();
    for (int o = 128; o; o >>= 1) {
        if (tid < o) red[tid] += red[tid + o];
        __syncthreads();
    }
    const float inv = 1.0f / red[0];
    splitw(v0 * inv, oh + base + tid,       ol + base + tid);
    splitw(v1 * inv, oh + base + tid + 256, ol + base + tid + 256);
}

// ---------------------------------------------------------------------------
// (optional residual) + LayerNorm (+ split). One block per token.
// ---------------------------------------------------------------------------
__global__ void ln_k(const float* __restrict__ src, float* __restrict__ h,
                     __nv_bfloat16* __restrict__ hh, __nv_bfloat16* __restrict__ hl,
                     const float* __restrict__ w, const float* __restrict__ b,
                     int residual)
{
    const int token = blockIdx.x;
    const size_t base = (size_t)token * KD;
    const int tid = threadIdx.x;
    float x0 = src[base + tid];
    float x1 = src[base + tid + 256];
    if (residual) { x0 += h[base + tid]; x1 += h[base + tid + 256]; }
    __shared__ float s1[256], s2[256];
    s1[tid] = x0 + x1;
    s2[tid] = x0 * x0 + x1 * x1;
    __syncthreads();
    for (int o = 128; o; o >>= 1) {
        if (tid < o) { s1[tid] += s1[tid + o]; s2[tid] += s2[tid + o]; }
        __syncthreads();
    }
    const float mean = s1[0] * (1.f / KD);
    const float var  = s2[0] * (1.f / KD) - mean * mean;
    const float r = rsqrtf(var + 1e-5f);
    const float y0 = (x0 - mean) * r * w[tid]       + b[tid];
    const float y1 = (x1 - mean) * r * w[tid + 256] + b[tid + 256];
    h[base + tid]       = y0;
    h[base + tid + 256] = y1;
    splitw(y0, hh + base + tid,       hl + base + tid);
    splitw(y1, hh + base + tid + 256, hl + base + tid + 256);
}

// ---------------------------------------------------------------------------
// Host-side launcher
// ---------------------------------------------------------------------------
struct GemmArgs {
    const __nv_bfloat16 *Ah, *Al, *Bh, *Bl;
    const float* bias;
    float* C;
    __nv_bfloat16 *Ch, *Cl;
    int M, N, K, lda, ldb, ldc;
    long aO, aI, bO, bI, cO, cI;
    int zdiv, batches;
};

template<int EPI, int OUT>
static void launch_gemm(const GemmArgs& a)
{
    static bool attr_set = false;
    if (!attr_set) {
        cudaFuncSetAttribute(gemm_ps<EPI, OUT>,
                             cudaFuncAttributeMaxDynamicSharedMemorySize, GEMM_SMEM);
        attr_set = true;
    }
    dim3 grid(a.N / 128, a.M / 128, a.batches), block(256);
    gemm_ps<EPI, OUT><<<grid, block, GEMM_SMEM>>>(
        a.Ah, a.Al, a.Bh, a.Bl, a.bias, a.C, a.Ch, a.Cl,
        a.M, a.N, a.K, a.lda, a.ldb, a.ldc,
        a.aO, a.aI, a.bO, a.bI, a.cO, a.cI, a.zdiv);
}

extern "C" void kernel_launch(void* const* d_in, const int* in_sizes, int n_in,
                              void* d_out, int out_size)
{
    const int*   x        = (const int*)  d_in[0];
    const float* embed_W  = (const float*)d_in[1];
    const float* Wq       = (const float*)d_in[2];
    const float* Wk       = (const float*)d_in[3];
    const float* Wv       = (const float*)d_in[4];
    const float* Wu       = (const float*)d_in[5];
    const float* bu       = (const float*)d_in[6];
    const float* W1       = (const float*)d_in[7];
    const float* b1       = (const float*)d_in[8];
    const float* W2       = (const float*)d_in[9];
    const float* b2       = (const float*)d_in[10];
    const float* ln1_w    = (const float*)d_in[11];
    const float* ln1_b    = (const float*)d_in[12];
    const float* ln2_w    = (const float*)d_in[13];
    const float* ln2_b    = (const float*)d_in[14];
    const float* lnf_w    = (const float*)d_in[15];
    const float* lnf_b    = (const float*)d_in[16];
    const float* unembedW = (const float*)d_in[17];
    const float* unembedB = (const float*)d_in[18];
    float* out = (float*)d_out;

    float *h, *v, *att, *tmp;
    __nv_bfloat16 *hsh, *hsl, *wth, *wtl, *qsh, *qsl, *ksh, *ksl,
                  *vth, *vtl, *ash, *asl, *ysh, *ysl, *fsh, *fsl;
    cudaGetSymbolAddress((void**)&h,   g_h);
    cudaGetSymbolAddress((void**)&v,   g_v);
    cudaGetSymbolAddress((void**)&att, g_att);
    cudaGetSymbolAddress((void**)&tmp, g_tmp);
    cudaGetSymbolAddress((void**)&hsh, g_hs_h); cudaGetSymbolAddress((void**)&hsl, g_hs_l);
    cudaGetSymbolAddress((void**)&wth, g_wt_h); cudaGetSymbolAddress((void**)&wtl, g_wt_l);
    cudaGetSymbolAddress((void**)&qsh, g_qs_h); cudaGetSymbolAddress((void**)&qsl, g_qs_l);
    cudaGetSymbolAddress((void**)&ksh, g_ks_h); cudaGetSymbolAddress((void**)&ksl, g_ks_l);
    cudaGetSymbolAddress((void**)&vth, g_vt_h); cudaGetSymbolAddress((void**)&vtl, g_vt_l);
    cudaGetSymbolAddress((void**)&ash, g_as_h); cudaGetSymbolAddress((void**)&asl, g_as_l);
    cudaGetSymbolAddress((void**)&ysh, g_ys_h); cudaGetSymbolAddress((void**)&ysl, g_ys_l);
    cudaGetSymbolAddress((void**)&fsh, g_fs_h); cudaGetSymbolAddress((void**)&fsl, g_fs_l);

    embed_k<<<MTOK, 256>>>(x, embed_W, h, hsh, hsl);

    const long atI = (long)SEQ * SEQ;          // 262144
    const long atO = (long)HEADS * atI;

    for (int i = 0; i < NBLK; i++) {
        const float* Wq_i = Wq + (size_t)i * KD * HK;
        const float* Wk_i = Wk + (size_t)i * KD * HK;
        const float* Wv_i = Wv + (size_t)i * KD * HK;
        const float* Wu_i = Wu + (size_t)i * HK * KD;
        const float* bu_i = bu + (size_t)i * KD;
        const float* W1_i = W1 + (size_t)i * KD * FF;
        const float* b1_i = b1 + (size_t)i * FF;
        const float* W2_i = W2 + (size_t)i * FF * KD;
        const float* b2_i = b2 + (size_t)i * KD;

        // Q
        wconv<<<dim3(KD/32, HK/32), dim3(32,8)>>>(Wq_i, wth, wtl, KD, HK);
        { GemmArgs a = {hsh, hsl, wth, wtl, nullptr, nullptr, qsh, qsl,
                        MTOK, HK, KD, KD, KD, HK, 0,0,0,0,0,0, 1, 1};
          launch_gemm<0,1>(a); }
        // K
        wconv<<<dim3(KD/32, HK/32), dim3(32,8)>>>(Wk_i, wth, wtl, KD, HK);
        { GemmArgs a = {hsh, hsl, wth, wtl, nullptr, nullptr, ksh, ksl,
                        MTOK, HK, KD, KD, KD, HK, 0,0,0,0,0,0, 1, 1};
          launch_gemm<0,1>(a); }
        // V (fp32, will be transposed)
        wconv<<<dim3(KD/32, HK/32), dim3(32,8)>>>(Wv_i, wth, wtl, KD, HK);
        { GemmArgs a = {hsh, hsl, wth, wtl, nullptr, v, nullptr, nullptr,
                        MTOK, HK, KD, KD, KD, HK, 0,0,0,0,0,0, 1, 1};
          launch_gemm<0,0>(a); }

        // scores = Q @ K^T   (z = b*8+h)
        { GemmArgs a = {qsh, qsl, ksh, ksl, nullptr, att, nullptr, nullptr,
                        SEQ, SEQ, KD, HK, HK, SEQ,
                        (long)SEQ*HK, (long)KD, (long)SEQ*HK, (long)KD,
                        atO, atI, HEADS, NBH};
          launch_gemm<0,0>(a); }

        softmax_k<<<dim3(SEQ, NBH), 256>>>(att, ash, asl);
        vconv<<<dim3(16,16,NBH), dim3(32,8)>>>(v, vth, vtl);

        // y = att @ V
        { GemmArgs a = {ash, asl, vth, vtl, nullptr, nullptr, ysh, ysl,
                        SEQ, KD, SEQ, SEQ, SEQ, HK,
                        atO, atI, atO, atI,
                        (long)SEQ*HK, (long)KD, HEADS, NBH};
          launch_gemm<0,1>(a); }

        // proj: tmp = y @ Wu + bu
        wconv<<<dim3(HK/32, KD/32), dim3(32,8)>>>(Wu_i, wth, wtl, HK, KD);
        { GemmArgs a = {ysh, ysl, wth, wtl, bu_i, tmp, nullptr, nullptr,
                        MTOK, KD, HK, HK, HK, KD, 0,0,0,0,0,0, 1, 1};
          launch_gemm<1,0>(a); }

        ln_k<<<MTOK, 256>>>(tmp, h, hsh, hsl,
                            ln1_w + (size_t)i * KD, ln1_b + (size_t)i * KD, 1);

        // ff = gelu(h @ W1 + b1)   (split output)
        wconv<<<dim3(KD/32, FF/32), dim3(32,8)>>>(W1_i, wth, wtl, KD, FF);
        { GemmArgs a = {hsh, hsl, wth, wtl, b1_i, nullptr, fsh, fsl,
                        MTOK, FF, KD, KD, KD, FF, 0,0,0,0,0,0, 1, 1};
          launch_gemm<2,1>(a); }

        // tmp = ff @ W2 + b2
        wconv<<<dim3(FF/32, KD/32), dim3(32,8)>>>(W2_i, wth, wtl, FF, KD);
        { GemmArgs a = {fsh, fsl, wth, wtl, b2_i, tmp, nullptr, nullptr,
                        MTOK, KD, FF, FF, FF, KD, 0,0,0,0,0,0, 1, 1};
          launch_gemm<1,0>(a); }

        ln_k<<<MTOK, 256>>>(tmp, h, hsh, hsl,
                            ln2_w + (size_t)i * KD, ln2_b + (size_t)i * KD, 1);
    }

    ln_k<<<MTOK, 256>>>(h, h, hsh, hsl, lnf_w, lnf_b, 0);

    // unembed
    wconv<<<dim3(KD/32, VOCAB/32), dim3(32,8)>>>(unembedW, wth, wtl, KD, VOCAB);
    { GemmArgs a = {hsh, hsl, wth, wtl, unembedB, out, nullptr, nullptr,
                    MTOK, VOCAB, KD, KD, KD, VOCAB, 0,0,0,0,0,0, 1, 1};
      launch_gemm<1,0>(a); }
}

// round 7
// speedup vs baseline: 2.4074x; 1.0609x over previous
#include <cuda_runtime.h>
#include <cuda_bf16.h>
#include <math.h>

// ---------------------------------------------------------------------------
// GPT forward. Pre-split bf16x3 tensor-core GEMMs with cp.async pipeline.
// B=4, T=512, K=512, H=8, NB=4, VOCAB=32000. M = B*T = 2048 tokens.
//
// All GEMM operands are pre-split packed bf16 (hi = bf16(x), lo = bf16(x-hi)),
// both A and B stored k-contiguous. GEMM = cp.async 3-stage pipeline +
// ldmatrix + 3x mma.m16n8k16.bf16 (Ah*Bh + Ah*Bl + Al*Bh).
// 2 CTAs/SM (96KB smem, <=128 regs) for issue-latency hiding.
// ---------------------------------------------------------------------------

#define BATCH 4
#define SEQ   512
#define KD    512
#define HEADS 8
#define NBLK  4
#define VOCAB 32000
#define MTOK  (BATCH*SEQ)        // 2048
#define HK    (HEADS*KD)         // 4096
#define FF    (4*KD)             // 2048
#define NBH   (BATCH*HEADS)      // 32

// fp32 scratch
__device__ float g_h  [MTOK*KD];
__device__ float g_v  [MTOK*HK];
__device__ float g_att[NBH*SEQ*SEQ];
__device__ float g_tmp[MTOK*KD];
// split bf16 scratch
__device__ __align__(256) __nv_bfloat16 g_hs_h[MTOK*KD],  g_hs_l[MTOK*KD];
__device__ __align__(256) __nv_bfloat16 g_wt_h[(size_t)VOCAB*KD], g_wt_l[(size_t)VOCAB*KD];
__device__ __align__(256) __nv_bfloat16 g_qs_h[MTOK*HK],  g_qs_l[MTOK*HK];
__device__ __align__(256) __nv_bfloat16 g_ks_h[MTOK*HK],  g_ks_l[MTOK*HK];
__device__ __align__(256) __nv_bfloat16 g_vt_h[MTOK*HK],  g_vt_l[MTOK*HK];
__device__ __align__(256) __nv_bfloat16 g_as_h[NBH*SEQ*SEQ], g_as_l[NBH*SEQ*SEQ];
__device__ __align__(256) __nv_bfloat16 g_ys_h[MTOK*HK],  g_ys_l[MTOK*HK];
__device__ __align__(256) __nv_bfloat16 g_fs_h[MTOK*FF],  g_fs_l[MTOK*FF];

// ---------------------------------------------------------------------------
// helpers
// ---------------------------------------------------------------------------
__device__ __forceinline__ unsigned smem_u32(const void* p) {
    unsigned r;
    asm("{ .reg .u64 t; cvta.to.shared.u64 t, %1; cvt.u32.u64 %0, t; }"
        : "=r"(r) : "l"(p));
    return r;
}
__device__ __forceinline__ void cp16(unsigned dst, const void* src) {
    asm volatile("cp.async.cg.shared.global [%0], [%1], 16;" :: "r"(dst), "l"(src));
}
#define CP_COMMIT() asm volatile("cp.async.commit_group;" ::: "memory")
#define CP_WAIT1()  asm volatile("cp.async.wait_group 1;" ::: "memory")

__device__ __forceinline__ void ldsm4(unsigned addr, unsigned& r0, unsigned& r1,
                                      unsigned& r2, unsigned& r3) {
    asm volatile("ldmatrix.sync.aligned.m8n8.x4.shared.b16 {%0,%1,%2,%3}, [%4];"
                 : "=r"(r0), "=r"(r1), "=r"(r2), "=r"(r3) : "r"(addr));
}
__device__ __forceinline__ void ldsm2(unsigned addr, unsigned& r0, unsigned& r1) {
    asm volatile("ldmatrix.sync.aligned.m8n8.x2.shared.b16 {%0,%1}, [%2];"
                 : "=r"(r0), "=r"(r1) : "r"(addr));
}
__device__ __forceinline__ void mma16(float* c, const unsigned* a, const unsigned* b) {
    asm volatile(
        "mma.sync.aligned.m16n8k16.row.col.f32.bf16.bf16.f32 "
        "{%0,%1,%2,%3},{%4,%5,%6,%7},{%8,%9},{%0,%1,%2,%3};"
        : "+f"(c[0]), "+f"(c[1]), "+f"(c[2]), "+f"(c[3])
        : "r"(a[0]), "r"(a[1]), "r"(a[2]), "r"(a[3]), "r"(b[0]), "r"(b[1]));
}
__device__ __forceinline__ void splitw(float v, __nv_bfloat16* ph, __nv_bfloat16* pl) {
    __nv_bfloat16 hi = __float2bfloat16(v);
    *ph = hi;
    *pl = __float2bfloat16(v - __bfloat162float(hi));
}
__device__ __forceinline__ void split2(float a, float b,
                                       __nv_bfloat162& H, __nv_bfloat162& L) {
    __nv_bfloat16 ha = __float2bfloat16(a), hb = __float2bfloat16(b);
    H = __halves2bfloat162(ha, hb);
    L = __halves2bfloat162(__float2bfloat16(a - __bfloat162float(ha)),
                           __float2bfloat16(b - __bfloat162float(hb)));
}

// SMEM stage layout (uint32 units): [AH 2048 | AL 2048 | BH 2048 | BL 2048]
// Tile row = 16 uint32 (32 bf16 along k), swizzle col' = c ^ ((row&6)<<1).
#define ST_U32 8192
#define AH_OFF 0
#define AL_OFF 2048
#define BH_OFF 4096
#define BL_OFF 6144
#define NSTAGE 3
#define GEMM_SMEM (NSTAGE*ST_U32*4)   // 98304 bytes

// ---------------------------------------------------------------------------
// Pipelined split-bf16 GEMM.
//  A (hi/lo): [M][K] bf16, lda.   B (hi/lo): [N][K] bf16, ldb.
//  C = A * B^T(logical) with epilogue:
//   EPI: 0 none, 1 +bias, 2 gelu(x+bias)
//   OUT: 0 -> fp32 C;  1 -> split bf16 Ch/Cl (same [M][N] layout)
// Batched via blockIdx.z (zdiv decomposition), strides in elements.
// Requires M%128==0, N%128==0, K%32==0, K>=96.
// ---------------------------------------------------------------------------
template<int EPI, int OUT>
__global__ __launch_bounds__(256, 2)
void gemm_ps(const __nv_bfloat16* __restrict__ Ah, const __nv_bfloat16* __restrict__ Al,
             const __nv_bfloat16* __restrict__ Bh, const __nv_bfloat16* __restrict__ Bl,
             const float* __restrict__ bias,
             float* __restrict__ C,
             __nv_bfloat16* __restrict__ Ch, __nv_bfloat16* __restrict__ Cl,
             int M, int N, int K, int lda, int ldb, int ldc,
             long aO, long aI, long bO, long bI, long cO, long cI, int zdiv)
{
    extern __shared__ unsigned sm[];
    const unsigned base32 = smem_u32(sm);

    const int z  = blockIdx.z;
    const int zb = z / zdiv, zh = z - zb * zdiv;
    const size_t aoff = (size_t)zb * aO + (size_t)zh * aI;
    const size_t boff = (size_t)zb * bO + (size_t)zh * bI;
    const size_t coff = (size_t)zb * cO + (size_t)zh * cI;
    Ah += aoff; Al += aoff; Bh += boff; Bl += boff;

    const int tid  = threadIdx.x;
    const int lane = tid & 31;
    const int warp = tid >> 5;
    const int g    = lane >> 2;
    const int tc   = lane & 3;
    const int wm   = (warp >> 2) * 64;
    const int wn   = (warp & 3) * 32;
    const int bx   = blockIdx.x, by = blockIdx.y;

    // cp.async mapping: thread -> tile row (tid>>1), granule pair (tid&1)*2
    const int crow = tid >> 1;
    const int cj   = (tid & 1) * 2;
    const __nv_bfloat16* pAh = Ah + (size_t)(by * 128 + crow) * lda + cj * 8;
    const __nv_bfloat16* pAl = Al + (size_t)(by * 128 + crow) * lda + cj * 8;
    const __nv_bfloat16* pBh = Bh + (size_t)(bx * 128 + crow) * ldb + cj * 8;
    const __nv_bfloat16* pBl = Bl + (size_t)(bx * 128 + crow) * ldb + cj * 8;
    const int csw = (crow & 6) << 1;
    const int cs0 = crow * 16 + ((4 * cj)     ^ csw);
    const int cs1 = crow * 16 + ((4 * cj + 4) ^ csw);

    // ldmatrix source indices (uint32 units, region-relative)
    int idxA[4][2], idxB[4][2];
    {
        const int rowA = wm + (lane & 15);
        const int cgA0 = (lane >> 4) << 2;
        const int rowB = wn + (lane & 7);
        const int cgB0 = ((lane >> 3) & 1) << 2;
        #pragma unroll
        for (int mf = 0; mf < 4; mf++) {
            const int r = rowA + mf * 16;
            idxA[mf][0] = r * 16 + ((cgA0)     ^ ((r & 6) << 1));
            idxA[mf][1] = r * 16 + ((cgA0 + 8) ^ ((r & 6) << 1));
        }
        #pragma unroll
        for (int nf = 0; nf < 4; nf++) {
            const int r = rowB + nf * 8;
            idxB[nf][0] = r * 16 + ((cgB0)     ^ ((r & 6) << 1));
            idxB[nf][1] = r * 16 + ((cgB0 + 8) ^ ((r & 6) << 1));
        }
    }

    float acc[4][4][4];
    #pragma unroll
    for (int i = 0; i < 4; i++)
        #pragma unroll
        for (int j = 0; j < 4; j++)
            #pragma unroll
            for (int r = 0; r < 4; r++) acc[i][j][r] = 0.f;

    auto ISSUE = [&](int buf, int k0) {
        const unsigned sb = base32 + buf * (ST_U32 * 4);
        cp16(sb + (AH_OFF + cs0) * 4, pAh + k0);
        cp16(sb + (AH_OFF + cs1) * 4, pAh + k0 + 8);
        cp16(sb + (AL_OFF + cs0) * 4, pAl + k0);
        cp16(sb + (AL_OFF + cs1) * 4, pAl + k0 + 8);
        cp16(sb + (BH_OFF + cs0) * 4, pBh + k0);
        cp16(sb + (BH_OFF + cs1) * 4, pBh + k0 + 8);
        cp16(sb + (BL_OFF + cs0) * 4, pBl + k0);
        cp16(sb + (BL_OFF + cs1) * 4, pBl + k0 + 8);
    };

    const int nc = K >> 5;

    ISSUE(0, 0);  CP_COMMIT();
    ISSUE(1, 32); CP_COMMIT();

    for (int i = 0; i < nc; i++) {
        CP_WAIT1();            // chunk i resident
        __syncthreads();

        const unsigned stb = base32 + (i % NSTAGE) * (ST_U32 * 4);
        #pragma unroll
        for (int kpb = 0; kpb < 2; kpb++) {
            unsigned Bf[4][2], Mf[4][2];
            #pragma unroll
            for (int nf = 0; nf < 4; nf++) {
                ldsm2(stb + (BH_OFF + idxB[nf][kpb]) * 4, Bf[nf][0], Bf[nf][1]);
                ldsm2(stb + (BL_OFF + idxB[nf][kpb]) * 4, Mf[nf][0], Mf[nf][1]);
            }
            #pragma unroll
            for (int mf = 0; mf < 4; mf++) {
                unsigned Aa[4], Ll[4];
                ldsm4(stb + (AH_OFF + idxA[mf][kpb]) * 4, Aa[0], Aa[1], Aa[2], Aa[3]);
                ldsm4(stb + (AL_OFF + idxA[mf][kpb]) * 4, Ll[0], Ll[1], Ll[2], Ll[3]);
                #pragma unroll
                for (int nf = 0; nf < 4; nf++) {
                    mma16(acc[mf][nf], Aa, Mf[nf]);
                    mma16(acc[mf][nf], Ll, Bf[nf]);
                    mma16(acc[mf][nf], Aa, Bf[nf]);
                }
            }
        }
        __syncthreads();       // all warps done with buffer (i+2)%NSTAGE's old data
        if (i + 2 < nc) ISSUE((i + 2) % NSTAGE, (i + 2) * 32);
        CP_COMMIT();
    }

    // ---- epilogue ----
    #pragma unroll
    for (int mf = 0; mf < 4; mf++) {
        const int r0 = by * 128 + wm + mf * 16 + g;
        #pragma unroll
        for (int nf = 0; nf < 4; nf++) {
            const int col = bx * 128 + wn + nf * 8 + tc * 2;
            float c0 = acc[mf][nf][0], c1 = acc[mf][nf][1];
            float c2 = acc[mf][nf][2], c3 = acc[mf][nf][3];
            if (EPI >= 1) {
                const float b0v = bias[col], b1v = bias[col + 1];
                c0 += b0v; c1 += b1v; c2 += b0v; c3 += b1v;
            }
            if (EPI == 2) {
                c0 = 0.5f * c0 * (1.0f + erff(c0 * 0.7071067811865475f));
                c1 = 0.5f * c1 * (1.0f + erff(c1 * 0.7071067811865475f));
                c2 = 0.5f * c2 * (1.0f + erff(c2 * 0.7071067811865475f));
                c3 = 0.5f * c3 * (1.0f + erff(c3 * 0.7071067811865475f));
            }
            if (OUT == 0) {
                *(float2*)&C[coff + (size_t)r0 * ldc + col]       = make_float2(c0, c1);
                *(float2*)&C[coff + (size_t)(r0 + 8) * ldc + col] = make_float2(c2, c3);
            } else {
                __nv_bfloat162 H, L;
                split2(c0, c1, H, L);
                *(__nv_bfloat162*)&Ch[coff + (size_t)r0 * ldc + col] = H;
                *(__nv_bfloat162*)&Cl[coff + (size_t)r0 * ldc + col] = L;
                split2(c2, c3, H, L);
                *(__nv_bfloat162*)&Ch[coff + (size_t)(r0 + 8) * ldc + col] = H;
                *(__nv_bfloat162*)&Cl[coff + (size_t)(r0 + 8) * ldc + col] = L;
            }
        }
    }
}

// ---------------------------------------------------------------------------
// Weight transpose + split: src fp32 [K][N] -> dst bf16 hi/lo [N][K].
// grid (K/32, N/32), block (32,8).
// ---------------------------------------------------------------------------
__global__ void wconv(const float* __restrict__ src,
                      __nv_bfloat16* __restrict__ dh, __nv_bfloat16* __restrict__ dl,
                      int K, int N)
{
    __shared__ float t[32][33];
    const int k0 = blockIdx.x * 32, n0 = blockIdx.y * 32;
    const int tx = threadIdx.x, ty = threadIdx.y;
    #pragma unroll
    for (int r = 0; r < 4; r++)
        t[ty + r * 8][tx] = src[(size_t)(k0 + ty + r * 8) * N + n0 + tx];
    __syncthreads();
    #pragma unroll
    for (int r = 0; r < 4; r++) {
        const float v = t[tx][ty + r * 8];
        const size_t o = (size_t)(n0 + ty + r * 8) * K + k0 + tx;
        splitw(v, dh + o, dl + o);
    }
}

// ---------------------------------------------------------------------------
// V transpose + split per head: v fp32 [b*t][h*d] -> vt [(b*8+h)*512+d][t].
// grid (16,16,32), block (32,8).
// ---------------------------------------------------------------------------
__global__ void vconv(const float* __restrict__ v,
                      __nv_bfloat16* __restrict__ dh, __nv_bfloat16* __restrict__ dl)
{
    __shared__ float t[32][33];
    const int z = blockIdx.z, b = z >> 3, h = z & 7;
    const int t0 = blockIdx.x * 32, d0 = blockIdx.y * 32;
    const int tx = threadIdx.x, ty = threadIdx.y;
    #pragma unroll
    for (int r = 0; r < 4; r++)
        t[ty + r * 8][tx] = v[(size_t)(b * SEQ + t0 + ty + r * 8) * HK + h * KD + d0 + tx];
    __syncthreads();
    #pragma unroll
    for (int r = 0; r < 4; r++) {
        const float val = t[tx][ty + r * 8];
        const size_t o = ((size_t)z * KD + d0 + ty + r * 8) * SEQ + t0 + tx;
        splitw(val, dh + o, dl + o);
    }
}

// ---------------------------------------------------------------------------
// Embedding + positional encoding (+ split). One block per token.
// ---------------------------------------------------------------------------
__global__ void embed_k(const int* __restrict__ x, const float* __restrict__ W,
                        float* __restrict__ h,
                        __nv_bfloat16* __restrict__ hh, __nv_bfloat16* __restrict__ hl)
{
    const int token = blockIdx.x;
    const int t  = token & (SEQ - 1);
    const int id = x[token];
    const int tid = threadIdx.x;
    #pragma unroll
    for (int u = 0; u < 2; u++) {
        const int c = tid + u * 256;
        const int j = c >> 1;
        const float ang = (float)t * expf(-(float)j * 0.07195578415606394f);
        const float p = (c & 1) ? cosf(ang) : sinf(ang);
        const float val = W[(size_t)id * KD + c] + p;
        const size_t o = (size_t)token * KD + c;
        h[o] = val;
        splitw(val, hh + o, hl + o);
    }
}

// ---------------------------------------------------------------------------
// Causal softmax (scale folded), writes split bf16. grid(SEQ, 32), 256 thr.
// ---------------------------------------------------------------------------
__global__ void softmax_k(const float* __restrict__ att,
                          __nv_bfloat16* __restrict__ oh, __nv_bfloat16* __restrict__ ol)
{
    const int q  = blockIdx.x;
    const int bh = blockIdx.y;
    const size_t base = ((size_t)bh * SEQ + q) * SEQ;
    const int tid = threadIdx.x;
    const float scale = 0.04419417382415922f;  // 1/sqrt(512)
    __shared__ float red[256];

    const float s0 = (tid       <= q) ? att[base + tid]       * scale : -3.4e38f;
    const float s1 = (tid + 256 <= q) ? att[base + tid + 256] * scale : -3.4e38f;
    red[tid] = fmaxf(s0, s1);
    __syncthreads();
    for (int o = 128; o; o >>= 1) {
        if (tid < o) red[tid] = fmaxf(red[tid], red[tid + o]);
        __syncthreads();
    }
    const float m = red[0];
    __syncthreads();
    const float v0 = (tid       <= q) ? expf(s0 - m) : 0.f;
    const float v1 = (tid + 256 <= q) ? expf(s1 - m) : 0.f;
    red[tid] = v0 + v1;
    __syncthreads();
    for (int o = 128; o; o >>= 1) {
        if (tid < o) red[tid] += red[tid + o];
        __syncthreads();
    }
    const float inv = 1.0f / red[0];
    splitw(v0 * inv, oh + base + tid,       ol + base + tid);
    splitw(v1 * inv, oh + base + tid + 256, ol + base + tid + 256);
}

// ---------------------------------------------------------------------------
// (optional residual) + LayerNorm (+ split). One block per token.
// ---------------------------------------------------------------------------
__global__ void ln_k(const float* __restrict__ src, float* __restrict__ h,
                     __nv_bfloat16* __restrict__ hh, __nv_bfloat16* __restrict__ hl,
                     const float* __restrict__ w, const float* __restrict__ b,
                     int residual)
{
    const int token = blockIdx.x;
    const size_t base = (size_t)token * KD;
    const int tid = threadIdx.x;
    float x0 = src[base + tid];
    float x1 = src[base + tid + 256];
    if (residual) { x0 += h[base + tid]; x1 += h[base + tid + 256]; }
    __shared__ float s1[256], s2[256];
    s1[tid] = x0 + x1;
    s2[tid] = x0 * x0 + x1 * x1;
    __syncthreads();
    for (int o = 128; o; o >>= 1) {
        if (tid < o) { s1[tid] += s1[tid + o]; s2[tid] += s2[tid + o]; }
        __syncthreads();
    }
    const float mean = s1[0] * (1.f / KD);
    const float var  = s2[0] * (1.f / KD) - mean * mean;
    const float r = rsqrtf(var + 1e-5f);
    const float y0 = (x0 - mean) * r * w[tid]       + b[tid];
    const float y1 = (x1 - mean) * r * w[tid + 256] + b[tid + 256];
    h[base + tid]       = y0;
    h[base + tid + 256] = y1;
    splitw(y0, hh + base + tid,       hl + base + tid);
    splitw(y1, hh + base + tid + 256, hl + base + tid + 256);
}

// ---------------------------------------------------------------------------
// Host-side launcher
// ---------------------------------------------------------------------------
struct GemmArgs {
    const __nv_bfloat16 *Ah, *Al, *Bh, *Bl;
    const float* bias;
    float* C;
    __nv_bfloat16 *Ch, *Cl;
    int M, N, K, lda, ldb, ldc;
    long aO, aI, bO, bI, cO, cI;
    int zdiv, batches;
};

template<int EPI, int OUT>
static void launch_gemm(const GemmArgs& a)
{
    static bool attr_set = false;
    if (!attr_set) {
        cudaFuncSetAttribute(gemm_ps<EPI, OUT>,
                             cudaFuncAttributeMaxDynamicSharedMemorySize, GEMM_SMEM);
        attr_set = true;
    }
    dim3 grid(a.N / 128, a.M / 128, a.batches), block(256);
    gemm_ps<EPI, OUT><<<grid, block, GEMM_SMEM>>>(
        a.Ah, a.Al, a.Bh, a.Bl, a.bias, a.C, a.Ch, a.Cl,
        a.M, a.N, a.K, a.lda, a.ldb, a.ldc,
        a.aO, a.aI, a.bO, a.bI, a.cO, a.cI, a.zdiv);
}

extern "C" void kernel_launch(void* const* d_in, const int* in_sizes, int n_in,
                              void* d_out, int out_size)
{
    const int*   x        = (const int*)  d_in[0];
    const float* embed_W  = (const float*)d_in[1];
    const float* Wq       = (const float*)d_in[2];
    const float* Wk       = (const float*)d_in[3];
    const float* Wv       = (const float*)d_in[4];
    const float* Wu       = (const float*)d_in[5];
    const float* bu       = (const float*)d_in[6];
    const float* W1       = (const float*)d_in[7];
    const float* b1       = (const float*)d_in[8];
    const float* W2       = (const float*)d_in[9];
    const float* b2       = (const float*)d_in[10];
    const float* ln1_w    = (const float*)d_in[11];
    const float* ln1_b    = (const float*)d_in[12];
    const float* ln2_w    = (const float*)d_in[13];
    const float* ln2_b    = (const float*)d_in[14];
    const float* lnf_w    = (const float*)d_in[15];
    const float* lnf_b    = (const float*)d_in[16];
    const float* unembedW = (const float*)d_in[17];
    const float* unembedB = (const float*)d_in[18];
    float* out = (float*)d_out;

    float *h, *v, *att, *tmp;
    __nv_bfloat16 *hsh, *hsl, *wth, *wtl, *qsh, *qsl, *ksh, *ksl,
                  *vth, *vtl, *ash, *asl, *ysh, *ysl, *fsh, *fsl;
    cudaGetSymbolAddress((void**)&h,   g_h);
    cudaGetSymbolAddress((void**)&v,   g_v);
    cudaGetSymbolAddress((void**)&att, g_att);
    cudaGetSymbolAddress((void**)&tmp, g_tmp);
    cudaGetSymbolAddress((void**)&hsh, g_hs_h); cudaGetSymbolAddress((void**)&hsl, g_hs_l);
    cudaGetSymbolAddress((void**)&wth, g_wt_h); cudaGetSymbolAddress((void**)&wtl, g_wt_l);
    cudaGetSymbolAddress((void**)&qsh, g_qs_h); cudaGetSymbolAddress((void**)&qsl, g_qs_l);
    cudaGetSymbolAddress((void**)&ksh, g_ks_h); cudaGetSymbolAddress((void**)&ksl, g_ks_l);
    cudaGetSymbolAddress((void**)&vth, g_vt_h); cudaGetSymbolAddress((void**)&vtl, g_vt_l);
    cudaGetSymbolAddress((void**)&ash, g_as_h); cudaGetSymbolAddress((void**)&asl, g_as_l);
    cudaGetSymbolAddress((void**)&ysh, g_ys_h); cudaGetSymbolAddress((void**)&ysl, g_ys_l);
    cudaGetSymbolAddress((void**)&fsh, g_fs_h); cudaGetSymbolAddress((void**)&fsl, g_fs_l);

    embed_k<<<MTOK, 256>>>(x, embed_W, h, hsh, hsl);

    const long atI = (long)SEQ * SEQ;          // 262144
    const long atO = (long)HEADS * atI;

    for (int i = 0; i < NBLK; i++) {
        const float* Wq_i = Wq + (size_t)i * KD * HK;
        const float* Wk_i = Wk + (size_t)i * KD * HK;
        const float* Wv_i = Wv + (size_t)i * KD * HK;
        const float* Wu_i = Wu + (size_t)i * HK * KD;
        const float* bu_i = bu + (size_t)i * KD;
        const float* W1_i = W1 + (size_t)i * KD * FF;
        const float* b1_i = b1 + (size_t)i * FF;
        const float* W2_i = W2 + (size_t)i * FF * KD;
        const float* b2_i = b2 + (size_t)i * KD;

        // Q
        wconv<<<dim3(KD/32, HK/32), dim3(32,8)>>>(Wq_i, wth, wtl, KD, HK);
        { GemmArgs a = {hsh, hsl, wth, wtl, nullptr, nullptr, qsh, qsl,
                        MTOK, HK, KD, KD, KD, HK, 0,0,0,0,0,0, 1, 1};
          launch_gemm<0,1>(a); }
        // K
        wconv<<<dim3(KD/32, HK/32), dim3(32,8)>>>(Wk_i, wth, wtl, KD, HK);
        { GemmArgs a = {hsh, hsl, wth, wtl, nullptr, nullptr, ksh, ksl,
                        MTOK, HK, KD, KD, KD, HK, 0,0,0,0,0,0, 1, 1};
          launch_gemm<0,1>(a); }
        // V (fp32, will be transposed)
        wconv<<<dim3(KD/32, HK/32), dim3(32,8)>>>(Wv_i, wth, wtl, KD, HK);
        { GemmArgs a = {hsh, hsl, wth, wtl, nullptr, v, nullptr, nullptr,
                        MTOK, HK, KD, KD, KD, HK, 0,0,0,0,0,0, 1, 1};
          launch_gemm<0,0>(a); }

        // scores = Q @ K^T   (z = b*8+h)
        { GemmArgs a = {qsh, qsl, ksh, ksl, nullptr, att, nullptr, nullptr,
                        SEQ, SEQ, KD, HK, HK, SEQ,
                        (long)SEQ*HK, (long)KD, (long)SEQ*HK, (long)KD,
                        atO, atI, HEADS, NBH};
          launch_gemm<0,0>(a); }

        softmax_k<<<dim3(SEQ, NBH), 256>>>(att, ash, asl);
        vconv<<<dim3(16,16,NBH), dim3(32,8)>>>(v, vth, vtl);

        // y = att @ V
        { GemmArgs a = {ash, asl, vth, vtl, nullptr, nullptr, ysh, ysl,
                        SEQ, KD, SEQ, SEQ, SEQ, HK,
                        atO, atI, atO, atI,
                        (long)SEQ*HK, (long)KD, HEADS, NBH};
          launch_gemm<0,1>(a); }

        // proj: tmp = y @ Wu + bu
        wconv<<<dim3(HK/32, KD/32), dim3(32,8)>>>(Wu_i, wth, wtl, HK, KD);
        { GemmArgs a = {ysh, ysl, wth, wtl, bu_i, tmp, nullptr, nullptr,
                        MTOK, KD, HK, HK, HK, KD, 0,0,0,0,0,0, 1, 1};
          launch_gemm<1,0>(a); }

        ln_k<<<MTOK, 256>>>(tmp, h, hsh, hsl,
                            ln1_w + (size_t)i * KD, ln1_b + (size_t)i * KD, 1);

        // ff = gelu(h @ W1 + b1)   (split output)
        wconv<<<dim3(KD/32, FF/32), dim3(32,8)>>>(W1_i, wth, wtl, KD, FF);
        { GemmArgs a = {hsh, hsl, wth, wtl, b1_i, nullptr, fsh, fsl,
                        MTOK, FF, KD, KD, KD, FF, 0,0,0,0,0,0, 1, 1};
          launch_gemm<2,1>(a); }

        // tmp = ff @ W2 + b2
        wconv<<<dim3(FF/32, KD/32), dim3(32,8)>>>(W2_i, wth, wtl, FF, KD);
        { GemmArgs a = {fsh, fsl, wth, wtl, b2_i, tmp, nullptr, nullptr,
                        MTOK, KD, FF, FF, FF, KD, 0,0,0,0,0,0, 1, 1};
          launch_gemm<1,0>(a); }

        ln_k<<<MTOK, 256>>>(tmp, h, hsh, hsl,
                            ln2_w + (size_t)i * KD, ln2_b + (size_t)i * KD, 1);
    }

    ln_k<<<MTOK, 256>>>(h, h, hsh, hsl, lnf_w, lnf_b, 0);

    // unembed
    wconv<<<dim3(KD/32, VOCAB/32), dim3(32,8)>>>(unembedW, wth, wtl, KD, VOCAB);
    { GemmArgs a = {hsh, hsl, wth, wtl, unembedB, out, nullptr, nullptr,
                    MTOK, VOCAB, KD, KD, KD, VOCAB, 0,0,0,0,0,0, 1, 1};
      launch_gemm<1,0>(a); }
}

// round 8
// speedup vs baseline: 2.5935x; 1.0773x over previous
#include <cuda_runtime.h>
#include <cuda_bf16.h>
#include <math.h>

// ---------------------------------------------------------------------------
// GPT forward. Pre-split bf16x3 tensor-core GEMMs with cp.async pipeline.
// B=4, T=512, K=512, H=8, NB=4, VOCAB=32000. M = B*T = 2048 tokens.
//
// All GEMM operands are pre-split packed bf16 (hi = bf16(x), lo = bf16(x-hi)),
// both A and B stored k-contiguous. GEMM = cp.async 3-stage pipeline +
// ldmatrix + 3x mma.m16n8k16.bf16 (Ah*Bh + Ah*Bl + Al*Bh).
// 2 CTAs/SM; prefetch issued straight after the stage barrier (2-chunk
// headroom, single __syncthreads per chunk). Causal attention skips/truncates.
// ---------------------------------------------------------------------------

#define BATCH 4
#define SEQ   512
#define KD    512
#define HEADS 8
#define NBLK  4
#define VOCAB 32000
#define MTOK  (BATCH*SEQ)        // 2048
#define HK    (HEADS*KD)         // 4096
#define FF    (4*KD)             // 2048
#define NBH   (BATCH*HEADS)      // 32

// fp32 scratch
__device__ float g_h  [MTOK*KD];
__device__ float g_v  [MTOK*HK];
__device__ float g_att[NBH*SEQ*SEQ];
__device__ float g_tmp[MTOK*KD];
// split bf16 scratch
__device__ __align__(256) __nv_bfloat16 g_hs_h[MTOK*KD],  g_hs_l[MTOK*KD];
__device__ __align__(256) __nv_bfloat16 g_wt_h[(size_t)VOCAB*KD], g_wt_l[(size_t)VOCAB*KD];
__device__ __align__(256) __nv_bfloat16 g_qs_h[MTOK*HK],  g_qs_l[MTOK*HK];
__device__ __align__(256) __nv_bfloat16 g_ks_h[MTOK*HK],  g_ks_l[MTOK*HK];
__device__ __align__(256) __nv_bfloat16 g_vt_h[MTOK*HK],  g_vt_l[MTOK*HK];
__device__ __align__(256) __nv_bfloat16 g_as_h[NBH*SEQ*SEQ], g_as_l[NBH*SEQ*SEQ];
__device__ __align__(256) __nv_bfloat16 g_ys_h[MTOK*HK],  g_ys_l[MTOK*HK];
__device__ __align__(256) __nv_bfloat16 g_fs_h[MTOK*FF],  g_fs_l[MTOK*FF];

// ---------------------------------------------------------------------------
// helpers
// ---------------------------------------------------------------------------
__device__ __forceinline__ unsigned smem_u32(const void* p) {
    unsigned r;
    asm("{ .reg .u64 t; cvta.to.shared.u64 t, %1; cvt.u32.u64 %0, t; }"
        : "=r"(r) : "l"(p));
    return r;
}
__device__ __forceinline__ void cp16(unsigned dst, const void* src) {
    asm volatile("cp.async.cg.shared.global [%0], [%1], 16;" :: "r"(dst), "l"(src));
}
#define CP_COMMIT() asm volatile("cp.async.commit_group;" ::: "memory")
#define CP_WAIT1()  asm volatile("cp.async.wait_group 1;" ::: "memory")

__device__ __forceinline__ void ldsm4(unsigned addr, unsigned& r0, unsigned& r1,
                                      unsigned& r2, unsigned& r3) {
    asm volatile("ldmatrix.sync.aligned.m8n8.x4.shared.b16 {%0,%1,%2,%3}, [%4];"
                 : "=r"(r0), "=r"(r1), "=r"(r2), "=r"(r3) : "r"(addr));
}
__device__ __forceinline__ void ldsm2(unsigned addr, unsigned& r0, unsigned& r1) {
    asm volatile("ldmatrix.sync.aligned.m8n8.x2.shared.b16 {%0,%1}, [%2];"
                 : "=r"(r0), "=r"(r1) : "r"(addr));
}
__device__ __forceinline__ void mma16(float* c, const unsigned* a, const unsigned* b) {
    asm volatile(
        "mma.sync.aligned.m16n8k16.row.col.f32.bf16.bf16.f32 "
        "{%0,%1,%2,%3},{%4,%5,%6,%7},{%8,%9},{%0,%1,%2,%3};"
        : "+f"(c[0]), "+f"(c[1]), "+f"(c[2]), "+f"(c[3])
        : "r"(a[0]), "r"(a[1]), "r"(a[2]), "r"(a[3]), "r"(b[0]), "r"(b[1]));
}
__device__ __forceinline__ void splitw(float v, __nv_bfloat16* ph, __nv_bfloat16* pl) {
    __nv_bfloat16 hi = __float2bfloat16(v);
    *ph = hi;
    *pl = __float2bfloat16(v - __bfloat162float(hi));
}
__device__ __forceinline__ void split2(float a, float b,
                                       __nv_bfloat162& H, __nv_bfloat162& L) {
    __nv_bfloat16 ha = __float2bfloat16(a), hb = __float2bfloat16(b);
    H = __halves2bfloat162(ha, hb);
    L = __halves2bfloat162(__float2bfloat16(a - __bfloat162float(ha)),
                           __float2bfloat16(b - __bfloat162float(hb)));
}

// SMEM stage layout (uint32 units): [AH 2048 | AL 2048 | BH 2048 | BL 2048]
// Tile row = 16 uint32 (32 bf16 along k), swizzle col' = c ^ ((row&6)<<1).
#define ST_U32 8192
#define AH_OFF 0
#define AL_OFF 2048
#define BH_OFF 4096
#define BL_OFF 6144
#define NSTAGE 3
#define GEMM_SMEM (NSTAGE*ST_U32*4)   // 98304 bytes

// ---------------------------------------------------------------------------
// Pipelined split-bf16 GEMM.
//  A (hi/lo): [M][K] bf16, lda.   B (hi/lo): [N][K] bf16, ldb.
//  C = A * B^T(logical) with epilogue:
//   EPI: 0 none, 1 +bias, 2 gelu(x+bias)
//   OUT: 0 -> fp32 C;  1 -> split bf16 Ch/Cl (same [M][N] layout)
//  causal: 0 none; 1 skip tiles with bx>by (upper triangle); 2 truncate K
//          to (by+1)*128 (A columns beyond diagonal are zero).
// Batched via blockIdx.z (zdiv decomposition), strides in elements.
// Requires M%128==0, N%128==0, K%32==0, K_eff>=64.
// ---------------------------------------------------------------------------
template<int EPI, int OUT>
__global__ __launch_bounds__(256, 2)
void gemm_ps(const __nv_bfloat16* __restrict__ Ah, const __nv_bfloat16* __restrict__ Al,
             const __nv_bfloat16* __restrict__ Bh, const __nv_bfloat16* __restrict__ Bl,
             const float* __restrict__ bias,
             float* __restrict__ C,
             __nv_bfloat16* __restrict__ Ch, __nv_bfloat16* __restrict__ Cl,
             int M, int N, int K, int lda, int ldb, int ldc,
             long aO, long aI, long bO, long bI, long cO, long cI, int zdiv,
             int causal)
{
    extern __shared__ unsigned sm[];
    const unsigned base32 = smem_u32(sm);

    const int bx = blockIdx.x, by = blockIdx.y;
    if (causal == 1 && bx > by) return;
    if (causal == 2) K = min(K, (by + 1) * 128);

    const int z  = blockIdx.z;
    const int zb = z / zdiv, zh = z - zb * zdiv;
    const size_t aoff = (size_t)zb * aO + (size_t)zh * aI;
    const size_t boff = (size_t)zb * bO + (size_t)zh * bI;
    const size_t coff = (size_t)zb * cO + (size_t)zh * cI;
    Ah += aoff; Al += aoff; Bh += boff; Bl += boff;

    const int tid  = threadIdx.x;
    const int lane = tid & 31;
    const int warp = tid >> 5;
    const int g    = lane >> 2;
    const int tc   = lane & 3;
    const int wm   = (warp >> 2) * 64;
    const int wn   = (warp & 3) * 32;

    // cp.async mapping: thread -> tile row (tid>>1), granule pair (tid&1)*2
    const int crow = tid >> 1;
    const int cj   = (tid & 1) * 2;
    const __nv_bfloat16* pAh = Ah + (size_t)(by * 128 + crow) * lda + cj * 8;
    const __nv_bfloat16* pAl = Al + (size_t)(by * 128 + crow) * lda + cj * 8;
    const __nv_bfloat16* pBh = Bh + (size_t)(bx * 128 + crow) * ldb + cj * 8;
    const __nv_bfloat16* pBl = Bl + (size_t)(bx * 128 + crow) * ldb + cj * 8;
    const int csw = (crow & 6) << 1;
    const int cs0 = crow * 16 + ((4 * cj)     ^ csw);
    const int cs1 = crow * 16 + ((4 * cj + 4) ^ csw);

    // ldmatrix source indices (uint32 units, region-relative)
    int idxA[4][2], idxB[4][2];
    {
        const int rowA = wm + (lane & 15);
        const int cgA0 = (lane >> 4) << 2;
        const int rowB = wn + (lane & 7);
        const int cgB0 = ((lane >> 3) & 1) << 2;
        #pragma unroll
        for (int mf = 0; mf < 4; mf++) {
            const int r = rowA + mf * 16;
            idxA[mf][0] = r * 16 + ((cgA0)     ^ ((r & 6) << 1));
            idxA[mf][1] = r * 16 + ((cgA0 + 8) ^ ((r & 6) << 1));
        }
        #pragma unroll
        for (int nf = 0; nf < 4; nf++) {
            const int r = rowB + nf * 8;
            idxB[nf][0] = r * 16 + ((cgB0)     ^ ((r & 6) << 1));
            idxB[nf][1] = r * 16 + ((cgB0 + 8) ^ ((r & 6) << 1));
        }
    }

    float acc[4][4][4];
    #pragma unroll
    for (int i = 0; i < 4; i++)
        #pragma unroll
        for (int j = 0; j < 4; j++)
            #pragma unroll
            for (int r = 0; r < 4; r++) acc[i][j][r] = 0.f;

    auto ISSUE = [&](int buf, int k0) {
        const unsigned sb = base32 + buf * (ST_U32 * 4);
        cp16(sb + (AH_OFF + cs0) * 4, pAh + k0);
        cp16(sb + (AH_OFF + cs1) * 4, pAh + k0 + 8);
        cp16(sb + (AL_OFF + cs0) * 4, pAl + k0);
        cp16(sb + (AL_OFF + cs1) * 4, pAl + k0 + 8);
        cp16(sb + (BH_OFF + cs0) * 4, pBh + k0);
        cp16(sb + (BH_OFF + cs1) * 4, pBh + k0 + 8);
        cp16(sb + (BL_OFF + cs0) * 4, pBl + k0);
        cp16(sb + (BL_OFF + cs1) * 4, pBl + k0 + 8);
    };

    const int nc = K >> 5;

    ISSUE(0, 0);  CP_COMMIT();
    if (nc > 1) ISSUE(1, 32);
    CP_COMMIT();

    for (int i = 0; i < nc; i++) {
        CP_WAIT1();            // chunk i resident
        __syncthreads();       // warps also done computing chunk i-1

        // prefetch into buffer (i+2)%3 == (i-1)%3 (free after the barrier):
        // gives the load ~2 compute-phases of latency headroom.
        if (i + 2 < nc) ISSUE((i + 2) % NSTAGE, (i + 2) * 32);
        CP_COMMIT();

        const unsigned stb = base32 + (i % NSTAGE) * (ST_U32 * 4);
        #pragma unroll
        for (int kpb = 0; kpb < 2; kpb++) {
            unsigned Bf[4][2], Mf[4][2];
            #pragma unroll
            for (int nf = 0; nf < 4; nf++) {
                ldsm2(stb + (BH_OFF + idxB[nf][kpb]) * 4, Bf[nf][0], Bf[nf][1]);
                ldsm2(stb + (BL_OFF + idxB[nf][kpb]) * 4, Mf[nf][0], Mf[nf][1]);
            }
            #pragma unroll
            for (int mf = 0; mf < 4; mf++) {
                unsigned Aa[4], Ll[4];
                ldsm4(stb + (AH_OFF + idxA[mf][kpb]) * 4, Aa[0], Aa[1], Aa[2], Aa[3]);
                ldsm4(stb + (AL_OFF + idxA[mf][kpb]) * 4, Ll[0], Ll[1], Ll[2], Ll[3]);
                #pragma unroll
                for (int nf = 0; nf < 4; nf++) {
                    mma16(acc[mf][nf], Aa, Mf[nf]);
                    mma16(acc[mf][nf], Ll, Bf[nf]);
                    mma16(acc[mf][nf], Aa, Bf[nf]);
                }
            }
        }
    }

    // ---- epilogue ----
    #pragma unroll
    for (int mf = 0; mf < 4; mf++) {
        const int r0 = by * 128 + wm + mf * 16 + g;
        #pragma unroll
        for (int nf = 0; nf < 4; nf++) {
            const int col = bx * 128 + wn + nf * 8 + tc * 2;
            float c0 = acc[mf][nf][0], c1 = acc[mf][nf][1];
            float c2 = acc[mf][nf][2], c3 = acc[mf][nf][3];
            if (EPI >= 1) {
                const float b0v = bias[col], b1v = bias[col + 1];
                c0 += b0v; c1 += b1v; c2 += b0v; c3 += b1v;
            }
            if (EPI == 2) {
                c0 = 0.5f * c0 * (1.0f + erff(c0 * 0.7071067811865475f));
                c1 = 0.5f * c1 * (1.0f + erff(c1 * 0.7071067811865475f));
                c2 = 0.5f * c2 * (1.0f + erff(c2 * 0.7071067811865475f));
                c3 = 0.5f * c3 * (1.0f + erff(c3 * 0.7071067811865475f));
            }
            if (OUT == 0) {
                *(float2*)&C[coff + (size_t)r0 * ldc + col]       = make_float2(c0, c1);
                *(float2*)&C[coff + (size_t)(r0 + 8) * ldc + col] = make_float2(c2, c3);
            } else {
                __nv_bfloat162 H, L;
                split2(c0, c1, H, L);
                *(__nv_bfloat162*)&Ch[coff + (size_t)r0 * ldc + col] = H;
                *(__nv_bfloat162*)&Cl[coff + (size_t)r0 * ldc + col] = L;
                split2(c2, c3, H, L);
                *(__nv_bfloat162*)&Ch[coff + (size_t)(r0 + 8) * ldc + col] = H;
                *(__nv_bfloat162*)&Cl[coff + (size_t)(r0 + 8) * ldc + col] = L;
            }
        }
    }
}

// ---------------------------------------------------------------------------
// Weight transpose + split: src fp32 [K][N] -> dst bf16 hi/lo [N][K].
// grid (K/32, N/32), block (32,8).
// ---------------------------------------------------------------------------
__global__ void wconv(const float* __restrict__ src,
                      __nv_bfloat16* __restrict__ dh, __nv_bfloat16* __restrict__ dl,
                      int K, int N)
{
    __shared__ float t[32][33];
    const int k0 = blockIdx.x * 32, n0 = blockIdx.y * 32;
    const int tx = threadIdx.x, ty = threadIdx.y;
    #pragma unroll
    for (int r = 0; r < 4; r++)
        t[ty + r * 8][tx] = src[(size_t)(k0 + ty + r * 8) * N + n0 + tx];
    __syncthreads();
    #pragma unroll
    for (int r = 0; r < 4; r++) {
        const float v = t[tx][ty + r * 8];
        const size_t o = (size_t)(n0 + ty + r * 8) * K + k0 + tx;
        splitw(v, dh + o, dl + o);
    }
}

// ---------------------------------------------------------------------------
// V transpose + split per head: v fp32 [b*t][h*d] -> vt [(b*8+h)*512+d][t].
// grid (16,16,32), block (32,8).
// ---------------------------------------------------------------------------
__global__ void vconv(const float* __restrict__ v,
                      __nv_bfloat16* __restrict__ dh, __nv_bfloat16* __restrict__ dl)
{
    __shared__ float t[32][33];
    const int z = blockIdx.z, b = z >> 3, h = z & 7;
    const int t0 = blockIdx.x * 32, d0 = blockIdx.y * 32;
    const int tx = threadIdx.x, ty = threadIdx.y;
    #pragma unroll
    for (int r = 0; r < 4; r++)
        t[ty + r * 8][tx] = v[(size_t)(b * SEQ + t0 + ty + r * 8) * HK + h * KD + d0 + tx];
    __syncthreads();
    #pragma unroll
    for (int r = 0; r < 4; r++) {
        const float val = t[tx][ty + r * 8];
        const size_t o = ((size_t)z * KD + d0 + ty + r * 8) * SEQ + t0 + tx;
        splitw(val, dh + o, dl + o);
    }
}

// ---------------------------------------------------------------------------
// Embedding + positional encoding (+ split). One block per token.
// ---------------------------------------------------------------------------
__global__ void embed_k(const int* __restrict__ x, const float* __restrict__ W,
                        float* __restrict__ h,
                        __nv_bfloat16* __restrict__ hh, __nv_bfloat16* __restrict__ hl)
{
    const int token = blockIdx.x;
    const int t  = token & (SEQ - 1);
    const int id = x[token];
    const int tid = threadIdx.x;
    #pragma unroll
    for (int u = 0; u < 2; u++) {
        const int c = tid + u * 256;
        const int j = c >> 1;
        const float ang = (float)t * expf(-(float)j * 0.07195578415606394f);
        const float p = (c & 1) ? cosf(ang) : sinf(ang);
        const float val = W[(size_t)id * KD + c] + p;
        const size_t o = (size_t)token * KD + c;
        h[o] = val;
        splitw(val, hh + o, hl + o);
    }
}

// ---------------------------------------------------------------------------
// Causal softmax (scale folded), writes split bf16. grid(SEQ, 32), 256 thr.
// ---------------------------------------------------------------------------
__global__ void softmax_k(const float* __restrict__ att,
                          __nv_bfloat16* __restrict__ oh, __nv_bfloat16* __restrict__ ol)
{
    const int q  = blockIdx.x;
    const int bh = blockIdx.y;
    const size_t base = ((size_t)bh * SEQ + q) * SEQ;
    const int tid = threadIdx.x;
    const float scale = 0.04419417382415922f;  // 1/sqrt(512)
    __shared__ float red[256];

    const float s0 = (tid       <= q) ? att[base + tid]       * scale : -3.4e38f;
    const float s1 = (tid + 256 <= q) ? att[base + tid + 256] * scale : -3.4e38f;
    red[tid] = fmaxf(s0, s1);
    __syncthreads();
    for (int o = 128; o; o >>= 1) {
        if (tid < o) red[tid] = fmaxf(red[tid], red[tid + o]);
        __syncthreads();
    }
    const float m = red[0];
    __syncthreads();
    const float v0 = (tid       <= q) ? expf(s0 - m) : 0.f;
    const float v1 = (tid + 256 <= q) ? expf(s1 - m) : 0.f;
    red[tid] = v0 + v1;
    __syncthreads();
    for (int o = 128; o; o >>= 1) {
        if (tid < o) red[tid] += red[tid + o];
        __syncthreads();
    }
    const float inv = 1.0f / red[0];
    splitw(v0 * inv, oh + base + tid,       ol + base + tid);
    splitw(v1 * inv, oh + base + tid + 256, ol + base + tid + 256);
}

// ---------------------------------------------------------------------------
// (optional residual) + LayerNorm (+ split). One block per token.
// ---------------------------------------------------------------------------
__global__ void ln_k(const float* __restrict__ src, float* __restrict__ h,
                     __nv_bfloat16* __restrict__ hh, __nv_bfloat16* __restrict__ hl,
                     const float* __restrict__ w, const float* __restrict__ b,
                     int residual)
{
    const int token = blockIdx.x;
    const size_t base = (size_t)token * KD;
    const int tid = threadIdx.x;
    float x0 = src[base + tid];
    float x1 = src[base + tid + 256];
    if (residual) { x0 += h[base + tid]; x1 += h[base + tid + 256]; }
    __shared__ float s1[256], s2[256];
    s1[tid] = x0 + x1;
    s2[tid] = x0 * x0 + x1 * x1;
    __syncthreads();
    for (int o = 128; o; o >>= 1) {
        if (tid < o) { s1[tid] += s1[tid + o]; s2[tid] += s2[tid + o]; }
        __syncthreads();
    }
    const float mean = s1[0] * (1.f / KD);
    const float var  = s2[0] * (1.f / KD) - mean * mean;
    const float r = rsqrtf(var + 1e-5f);
    const float y0 = (x0 - mean) * r * w[tid]       + b[tid];
    const float y1 = (x1 - mean) * r * w[tid + 256] + b[tid + 256];
    h[base + tid]       = y0;
    h[base + tid + 256] = y1;
    splitw(y0, hh + base + tid,       hl + base + tid);
    splitw(y1, hh + base + tid + 256, hl + base + tid + 256);
}

// ---------------------------------------------------------------------------
// Host-side launcher
// ---------------------------------------------------------------------------
struct GemmArgs {
    const __nv_bfloat16 *Ah, *Al, *Bh, *Bl;
    const float* bias;
    float* C;
    __nv_bfloat16 *Ch, *Cl;
    int M, N, K, lda, ldb, ldc;
    long aO, aI, bO, bI, cO, cI;
    int zdiv, batches, causal;
};

template<int EPI, int OUT>
static void launch_gemm(const GemmArgs& a)
{
    static bool attr_set = false;
    if (!attr_set) {
        cudaFuncSetAttribute(gemm_ps<EPI, OUT>,
                             cudaFuncAttributeMaxDynamicSharedMemorySize, GEMM_SMEM);
        attr_set = true;
    }
    dim3 grid(a.N / 128, a.M / 128, a.batches), block(256);
    gemm_ps<EPI, OUT><<<grid, block, GEMM_SMEM>>>(
        a.Ah, a.Al, a.Bh, a.Bl, a.bias, a.C, a.Ch, a.Cl,
        a.M, a.N, a.K, a.lda, a.ldb, a.ldc,
        a.aO, a.aI, a.bO, a.bI, a.cO, a.cI, a.zdiv, a.causal);
}

extern "C" void kernel_launch(void* const* d_in, const int* in_sizes, int n_in,
                              void* d_out, int out_size)
{
    const int*   x        = (const int*)  d_in[0];
    const float* embed_W  = (const float*)d_in[1];
    const float* Wq       = (const float*)d_in[2];
    const float* Wk       = (const float*)d_in[3];
    const float* Wv       = (const float*)d_in[4];
    const float* Wu       = (const float*)d_in[5];
    const float* bu       = (const float*)d_in[6];
    const float* W1       = (const float*)d_in[7];
    const float* b1       = (const float*)d_in[8];
    const float* W2       = (const float*)d_in[9];
    const float* b2       = (const float*)d_in[10];
    const float* ln1_w    = (const float*)d_in[11];
    const float* ln1_b    = (const float*)d_in[12];
    const float* ln2_w    = (const float*)d_in[13];
    const float* ln2_b    = (const float*)d_in[14];
    const float* lnf_w    = (const float*)d_in[15];
    const float* lnf_b    = (const float*)d_in[16];
    const float* unembedW = (const float*)d_in[17];
    const float* unembedB = (const float*)d_in[18];
    float* out = (float*)d_out;

    float *h, *v, *att, *tmp;
    __nv_bfloat16 *hsh, *hsl, *wth, *wtl, *qsh, *qsl, *ksh, *ksl,
                  *vth, *vtl, *ash, *asl, *ysh, *ysl, *fsh, *fsl;
    cudaGetSymbolAddress((void**)&h,   g_h);
    cudaGetSymbolAddress((void**)&v,   g_v);
    cudaGetSymbolAddress((void**)&att, g_att);
    cudaGetSymbolAddress((void**)&tmp, g_tmp);
    cudaGetSymbolAddress((void**)&hsh, g_hs_h); cudaGetSymbolAddress((void**)&hsl, g_hs_l);
    cudaGetSymbolAddress((void**)&wth, g_wt_h); cudaGetSymbolAddress((void**)&wtl, g_wt_l);
    cudaGetSymbolAddress((void**)&qsh, g_qs_h); cudaGetSymbolAddress((void**)&qsl, g_qs_l);
    cudaGetSymbolAddress((void**)&ksh, g_ks_h); cudaGetSymbolAddress((void**)&ksl, g_ks_l);
    cudaGetSymbolAddress((void**)&vth, g_vt_h); cudaGetSymbolAddress((void**)&vtl, g_vt_l);
    cudaGetSymbolAddress((void**)&ash, g_as_h); cudaGetSymbolAddress((void**)&asl, g_as_l);
    cudaGetSymbolAddress((void**)&ysh, g_ys_h); cudaGetSymbolAddress((void**)&ysl, g_ys_l);
    cudaGetSymbolAddress((void**)&fsh, g_fs_h); cudaGetSymbolAddress((void**)&fsl, g_fs_l);

    embed_k<<<MTOK, 256>>>(x, embed_W, h, hsh, hsl);

    const long atI = (long)SEQ * SEQ;          // 262144
    const long atO = (long)HEADS * atI;

    for (int i = 0; i < NBLK; i++) {
        const float* Wq_i = Wq + (size_t)i * KD * HK;
        const float* Wk_i = Wk + (size_t)i * KD * HK;
        const float* Wv_i = Wv + (size_t)i * KD * HK;
        const float* Wu_i = Wu + (size_t)i * HK * KD;
        const float* bu_i = bu + (size_t)i * KD;
        const float* W1_i = W1 + (size_t)i * KD * FF;
        const float* b1_i = b1 + (size_t)i * FF;
        const float* W2_i = W2 + (size_t)i * FF * KD;
        const float* b2_i = b2 + (size_t)i * KD;

        // Q
        wconv<<<dim3(KD/32, HK/32), dim3(32,8)>>>(Wq_i, wth, wtl, KD, HK);
        { GemmArgs a = {hsh, hsl, wth, wtl, nullptr, nullptr, qsh, qsl,
                        MTOK, HK, KD, KD, KD, HK, 0,0,0,0,0,0, 1, 1, 0};
          launch_gemm<0,1>(a); }
        // K
        wconv<<<dim3(KD/32, HK/32), dim3(32,8)>>>(Wk_i, wth, wtl, KD, HK);
        { GemmArgs a = {hsh, hsl, wth, wtl, nullptr, nullptr, ksh, ksl,
                        MTOK, HK, KD, KD, KD, HK, 0,0,0,0,0,0, 1, 1, 0};
          launch_gemm<0,1>(a); }
        // V (fp32, will be transposed)
        wconv<<<dim3(KD/32, HK/32), dim3(32,8)>>>(Wv_i, wth, wtl, KD, HK);
        { GemmArgs a = {hsh, hsl, wth, wtl, nullptr, v, nullptr, nullptr,
                        MTOK, HK, KD, KD, KD, HK, 0,0,0,0,0,0, 1, 1, 0};
          launch_gemm<0,0>(a); }

        // scores = Q @ K^T   (z = b*8+h); skip upper-triangle tiles
        { GemmArgs a = {qsh, qsl, ksh, ksl, nullptr, att, nullptr, nullptr,
                        SEQ, SEQ, KD, HK, HK, SEQ,
                        (long)SEQ*HK, (long)KD, (long)SEQ*HK, (long)KD,
                        atO, atI, HEADS, NBH, 1};
          launch_gemm<0,0>(a); }

        softmax_k<<<dim3(SEQ, NBH), 256>>>(att, ash, asl);
        vconv<<<dim3(16,16,NBH), dim3(32,8)>>>(v, vth, vtl);

        // y = att @ V; att zero beyond diagonal -> truncate K per tile row
        { GemmArgs a = {ash, asl, vth, vtl, nullptr, nullptr, ysh, ysl,
                        SEQ, KD, SEQ, SEQ, SEQ, HK,
                        atO, atI, atO, atI,
                        (long)SEQ*HK, (long)KD, HEADS, NBH, 2};
          launch_gemm<0,1>(a); }

        // proj: tmp = y @ Wu + bu
        wconv<<<dim3(HK/32, KD/32), dim3(32,8)>>>(Wu_i, wth, wtl, HK, KD);
        { GemmArgs a = {ysh, ysl, wth, wtl, bu_i, tmp, nullptr, nullptr,
                        MTOK, KD, HK, HK, HK, KD, 0,0,0,0,0,0, 1, 1, 0};
          launch_gemm<1,0>(a); }

        ln_k<<<MTOK, 256>>>(tmp, h, hsh, hsl,
                            ln1_w + (size_t)i * KD, ln1_b + (size_t)i * KD, 1);

        // ff = gelu(h @ W1 + b1)   (split output)
        wconv<<<dim3(KD/32, FF/32), dim3(32,8)>>>(W1_i, wth, wtl, KD, FF);
        { GemmArgs a = {hsh, hsl, wth, wtl, b1_i, nullptr, fsh, fsl,
                        MTOK, FF, KD, KD, KD, FF, 0,0,0,0,0,0, 1, 1, 0};
          launch_gemm<2,1>(a); }

        // tmp = ff @ W2 + b2
        wconv<<<dim3(FF/32, KD/32), dim3(32,8)>>>(W2_i, wth, wtl, FF, KD);
        { GemmArgs a = {fsh, fsl, wth, wtl, b2_i, tmp, nullptr, nullptr,
                        MTOK, KD, FF, FF, FF, KD, 0,0,0,0,0,0, 1, 1, 0};
          launch_gemm<1,0>(a); }

        ln_k<<<MTOK, 256>>>(tmp, h, hsh, hsl,
                            ln2_w + (size_t)i * KD, ln2_b + (size_t)i * KD, 1);
    }

    ln_k<<<MTOK, 256>>>(h, h, hsh, hsl, lnf_w, lnf_b, 0);

    // unembed
    wconv<<<dim3(KD/32, VOCAB/32), dim3(32,8)>>>(unembedW, wth, wtl, KD, VOCAB);
    { GemmArgs a = {hsh, hsl, wth, wtl, unembedB, out, nullptr, nullptr,
                    MTOK, VOCAB, KD, KD, KD, VOCAB, 0,0,0,0,0,0, 1, 1, 0};
      launch_gemm<1,0>(a); }
}

// round 9
// speedup vs baseline: 3.0793x; 1.1873x over previous
#include <cuda_runtime.h>
#include <cuda_bf16.h>
#include <math.h>

// ---------------------------------------------------------------------------
// GPT forward. Pre-split bf16x3 tensor-core GEMMs with cp.async pipeline.
// B=4, T=512, K=512, H=8, NB=4, VOCAB=32000. M = B*T = 2048 tokens.
//
// R9: split-K (4 slices -> partial planes -> deterministic reduce) for the
// grid-starved skinny GEMMs (proj, MLP-W2); QKV fused into one N=12288 GEMM.
// ---------------------------------------------------------------------------

#define BATCH 4
#define SEQ   512
#define KD    512
#define HEADS 8
#define NBLK  4
#define VOCAB 32000
#define MTOK  (BATCH*SEQ)        // 2048
#define HK    (HEADS*KD)         // 4096
#define QKVN  (3*HK)             // 12288
#define FF    (4*KD)             // 2048
#define NBH   (BATCH*HEADS)      // 32

// fp32 scratch
__device__ float g_h  [MTOK*KD];
__device__ float g_att[NBH*SEQ*SEQ];      // scores; reused as split-K partials
__device__ float g_tmp[MTOK*KD];
// split bf16 scratch
__device__ __align__(256) __nv_bfloat16 g_hs_h[MTOK*KD],  g_hs_l[MTOK*KD];
__device__ __align__(256) __nv_bfloat16 g_wt_h[(size_t)VOCAB*KD], g_wt_l[(size_t)VOCAB*KD];
__device__ __align__(256) __nv_bfloat16 g_qkv_h[(size_t)MTOK*QKVN], g_qkv_l[(size_t)MTOK*QKVN];
__device__ __align__(256) __nv_bfloat16 g_vt_h[MTOK*HK],  g_vt_l[MTOK*HK];
__device__ __align__(256) __nv_bfloat16 g_as_h[NBH*SEQ*SEQ], g_as_l[NBH*SEQ*SEQ];
__device__ __align__(256) __nv_bfloat16 g_ys_h[MTOK*HK],  g_ys_l[MTOK*HK];
__device__ __align__(256) __nv_bfloat16 g_fs_h[MTOK*FF],  g_fs_l[MTOK*FF];

// ---------------------------------------------------------------------------
// helpers
// ---------------------------------------------------------------------------
__device__ __forceinline__ unsigned smem_u32(const void* p) {
    unsigned r;
    asm("{ .reg .u64 t; cvta.to.shared.u64 t, %1; cvt.u32.u64 %0, t; }"
        : "=r"(r) : "l"(p));
    return r;
}
__device__ __forceinline__ void cp16(unsigned dst, const void* src) {
    asm volatile("cp.async.cg.shared.global [%0], [%1], 16;" :: "r"(dst), "l"(src));
}
#define CP_COMMIT() asm volatile("cp.async.commit_group;" ::: "memory")
#define CP_WAIT1()  asm volatile("cp.async.wait_group 1;" ::: "memory")

__device__ __forceinline__ void ldsm4(unsigned addr, unsigned& r0, unsigned& r1,
                                      unsigned& r2, unsigned& r3) {
    asm volatile("ldmatrix.sync.aligned.m8n8.x4.shared.b16 {%0,%1,%2,%3}, [%4];"
                 : "=r"(r0), "=r"(r1), "=r"(r2), "=r"(r3) : "r"(addr));
}
__device__ __forceinline__ void ldsm2(unsigned addr, unsigned& r0, unsigned& r1) {
    asm volatile("ldmatrix.sync.aligned.m8n8.x2.shared.b16 {%0,%1}, [%2];"
                 : "=r"(r0), "=r"(r1) : "r"(addr));
}
__device__ __forceinline__ void mma16(float* c, const unsigned* a, const unsigned* b) {
    asm volatile(
        "mma.sync.aligned.m16n8k16.row.col.f32.bf16.bf16.f32 "
        "{%0,%1,%2,%3},{%4,%5,%6,%7},{%8,%9},{%0,%1,%2,%3};"
        : "+f"(c[0]), "+f"(c[1]), "+f"(c[2]), "+f"(c[3])
        : "r"(a[0]), "r"(a[1]), "r"(a[2]), "r"(a[3]), "r"(b[0]), "r"(b[1]));
}
__device__ __forceinline__ void splitw(float v, __nv_bfloat16* ph, __nv_bfloat16* pl) {
    __nv_bfloat16 hi = __float2bfloat16(v);
    *ph = hi;
    *pl = __float2bfloat16(v - __bfloat162float(hi));
}
__device__ __forceinline__ void split2(float a, float b,
                                       __nv_bfloat162& H, __nv_bfloat162& L) {
    __nv_bfloat16 ha = __float2bfloat16(a), hb = __float2bfloat16(b);
    H = __halves2bfloat162(ha, hb);
    L = __halves2bfloat162(__float2bfloat16(a - __bfloat162float(ha)),
                           __float2bfloat16(b - __bfloat162float(hb)));
}

// SMEM stage layout (uint32 units): [AH 2048 | AL 2048 | BH 2048 | BL 2048]
#define ST_U32 8192
#define AH_OFF 0
#define AL_OFF 2048
#define BH_OFF 4096
#define BL_OFF 6144
#define NSTAGE 3
#define GEMM_SMEM (NSTAGE*ST_U32*4)   // 98304 bytes

// ---------------------------------------------------------------------------
// Pipelined split-bf16 GEMM (see R8). causal: 0 none, 1 tile-skip, 2 K-trunc.
// Batched / split-K via blockIdx.z with (aO,aI,bO,bI,cO,cI,zdiv) strides.
// ---------------------------------------------------------------------------
template<int EPI, int OUT>
__global__ __launch_bounds__(256, 2)
void gemm_ps(const __nv_bfloat16* __restrict__ Ah, const __nv_bfloat16* __restrict__ Al,
             const __nv_bfloat16* __restrict__ Bh, const __nv_bfloat16* __restrict__ Bl,
             const float* __restrict__ bias,
             float* __restrict__ C,
             __nv_bfloat16* __restrict__ Ch, __nv_bfloat16* __restrict__ Cl,
             int M, int N, int K, int lda, int ldb, int ldc,
             long aO, long aI, long bO, long bI, long cO, long cI, int zdiv,
             int causal)
{
    extern __shared__ unsigned sm[];
    const unsigned base32 = smem_u32(sm);

    const int bx = blockIdx.x, by = blockIdx.y;
    if (causal == 1 && bx > by) return;
    if (causal == 2) K = min(K, (by + 1) * 128);

    const int z  = blockIdx.z;
    const int zb = z / zdiv, zh = z - zb * zdiv;
    const size_t aoff = (size_t)zb * aO + (size_t)zh * aI;
    const size_t boff = (size_t)zb * bO + (size_t)zh * bI;
    const size_t coff = (size_t)zb * cO + (size_t)zh * cI;
    Ah += aoff; Al += aoff; Bh += boff; Bl += boff;

    const int tid  = threadIdx.x;
    const int lane = tid & 31;
    const int warp = tid >> 5;
    const int g    = lane >> 2;
    const int tc   = lane & 3;
    const int wm   = (warp >> 2) * 64;
    const int wn   = (warp & 3) * 32;

    const int crow = tid >> 1;
    const int cj   = (tid & 1) * 2;
    const __nv_bfloat16* pAh = Ah + (size_t)(by * 128 + crow) * lda + cj * 8;
    const __nv_bfloat16* pAl = Al + (size_t)(by * 128 + crow) * lda + cj * 8;
    const __nv_bfloat16* pBh = Bh + (size_t)(bx * 128 + crow) * ldb + cj * 8;
    const __nv_bfloat16* pBl = Bl + (size_t)(bx * 128 + crow) * ldb + cj * 8;
    const int csw = (crow & 6) << 1;
    const int cs0 = crow * 16 + ((4 * cj)     ^ csw);
    const int cs1 = crow * 16 + ((4 * cj + 4) ^ csw);

    int idxA[4][2], idxB[4][2];
    {
        const int rowA = wm + (lane & 15);
        const int cgA0 = (lane >> 4) << 2;
        const int rowB = wn + (lane & 7);
        const int cgB0 = ((lane >> 3) & 1) << 2;
        #pragma unroll
        for (int mf = 0; mf < 4; mf++) {
            const int r = rowA + mf * 16;
            idxA[mf][0] = r * 16 + ((cgA0)     ^ ((r & 6) << 1));
            idxA[mf][1] = r * 16 + ((cgA0 + 8) ^ ((r & 6) << 1));
        }
        #pragma unroll
        for (int nf = 0; nf < 4; nf++) {
            const int r = rowB + nf * 8;
            idxB[nf][0] = r * 16 + ((cgB0)     ^ ((r & 6) << 1));
            idxB[nf][1] = r * 16 + ((cgB0 + 8) ^ ((r & 6) << 1));
        }
    }

    float acc[4][4][4];
    #pragma unroll
    for (int i = 0; i < 4; i++)
        #pragma unroll
        for (int j = 0; j < 4; j++)
            #pragma unroll
            for (int r = 0; r < 4; r++) acc[i][j][r] = 0.f;

    auto ISSUE = [&](int buf, int k0) {
        const unsigned sb = base32 + buf * (ST_U32 * 4);
        cp16(sb + (AH_OFF + cs0) * 4, pAh + k0);
        cp16(sb + (AH_OFF + cs1) * 4, pAh + k0 + 8);
        cp16(sb + (AL_OFF + cs0) * 4, pAl + k0);
        cp16(sb + (AL_OFF + cs1) * 4, pAl + k0 + 8);
        cp16(sb + (BH_OFF + cs0) * 4, pBh + k0);
        cp16(sb + (BH_OFF + cs1) * 4, pBh + k0 + 8);
        cp16(sb + (BL_OFF + cs0) * 4, pBl + k0);
        cp16(sb + (BL_OFF + cs1) * 4, pBl + k0 + 8);
    };

    const int nc = K >> 5;

    ISSUE(0, 0);  CP_COMMIT();
    if (nc > 1) ISSUE(1, 32);
    CP_COMMIT();

    for (int i = 0; i < nc; i++) {
        CP_WAIT1();
        __syncthreads();

        if (i + 2 < nc) ISSUE((i + 2) % NSTAGE, (i + 2) * 32);
        CP_COMMIT();

        const unsigned stb = base32 + (i % NSTAGE) * (ST_U32 * 4);
        #pragma unroll
        for (int kpb = 0; kpb < 2; kpb++) {
            unsigned Bf[4][2], Mf[4][2];
            #pragma unroll
            for (int nf = 0; nf < 4; nf++) {
                ldsm2(stb + (BH_OFF + idxB[nf][kpb]) * 4, Bf[nf][0], Bf[nf][1]);
                ldsm2(stb + (BL_OFF + idxB[nf][kpb]) * 4, Mf[nf][0], Mf[nf][1]);
            }
            #pragma unroll
            for (int mf = 0; mf < 4; mf++) {
                unsigned Aa[4], Ll[4];
                ldsm4(stb + (AH_OFF + idxA[mf][kpb]) * 4, Aa[0], Aa[1], Aa[2], Aa[3]);
                ldsm4(stb + (AL_OFF + idxA[mf][kpb]) * 4, Ll[0], Ll[1], Ll[2], Ll[3]);
                #pragma unroll
                for (int nf = 0; nf < 4; nf++) {
                    mma16(acc[mf][nf], Aa, Mf[nf]);
                    mma16(acc[mf][nf], Ll, Bf[nf]);
                    mma16(acc[mf][nf], Aa, Bf[nf]);
                }
            }
        }
    }

    // ---- epilogue ----
    #pragma unroll
    for (int mf = 0; mf < 4; mf++) {
        const int r0 = by * 128 + wm + mf * 16 + g;
        #pragma unroll
        for (int nf = 0; nf < 4; nf++) {
            const int col = bx * 128 + wn + nf * 8 + tc * 2;
            float c0 = acc[mf][nf][0], c1 = acc[mf][nf][1];
            float c2 = acc[mf][nf][2], c3 = acc[mf][nf][3];
            if (EPI >= 1) {
                const float b0v = bias[col], b1v = bias[col + 1];
                c0 += b0v; c1 += b1v; c2 += b0v; c3 += b1v;
            }
            if (EPI == 2) {
                c0 = 0.5f * c0 * (1.0f + erff(c0 * 0.7071067811865475f));
                c1 = 0.5f * c1 * (1.0f + erff(c1 * 0.7071067811865475f));
                c2 = 0.5f * c2 * (1.0f + erff(c2 * 0.7071067811865475f));
                c3 = 0.5f * c3 * (1.0f + erff(c3 * 0.7071067811865475f));
            }
            if (OUT == 0) {
                *(float2*)&C[coff + (size_t)r0 * ldc + col]       = make_float2(c0, c1);
                *(float2*)&C[coff + (size_t)(r0 + 8) * ldc + col] = make_float2(c2, c3);
            } else {
                __nv_bfloat162 H, L;
                split2(c0, c1, H, L);
                *(__nv_bfloat162*)&Ch[coff + (size_t)r0 * ldc + col] = H;
                *(__nv_bfloat162*)&Cl[coff + (size_t)r0 * ldc + col] = L;
                split2(c2, c3, H, L);
                *(__nv_bfloat162*)&Ch[coff + (size_t)(r0 + 8) * ldc + col] = H;
                *(__nv_bfloat162*)&Cl[coff + (size_t)(r0 + 8) * ldc + col] = L;
            }
        }
    }
}

// ---------------------------------------------------------------------------
// Split-K reduction: out = bias + sum of NS partial planes. float4 vectorized.
// ---------------------------------------------------------------------------
__global__ void reduce_k(const float* __restrict__ P, const float* __restrict__ bias,
                         float* __restrict__ out, int n, int total4)
{
    const int i = blockIdx.x * 256 + threadIdx.x;
    if (i >= total4) return;
    float4 a = ((const float4*)P)[i];
    #pragma unroll
    for (int s = 1; s < 4; s++) {
        float4 b = ((const float4*)P)[i + (size_t)s * total4];
        a.x += b.x; a.y += b.y; a.z += b.z; a.w += b.w;
    }
    const int c = (i * 4) & (n - 1);
    a.x += bias[c]; a.y += bias[c + 1]; a.z += bias[c + 2]; a.w += bias[c + 3];
    ((float4*)out)[i] = a;
}

// ---------------------------------------------------------------------------
// Weight transpose + split: src fp32 [K][N] -> dst bf16 hi/lo [N][K].
// ---------------------------------------------------------------------------
__global__ void wconv(const float* __restrict__ src,
                      __nv_bfloat16* __restrict__ dh, __nv_bfloat16* __restrict__ dl,
                      int K, int N)
{
    __shared__ float t[32][33];
    const int k0 = blockIdx.x * 32, n0 = blockIdx.y * 32;
    const int tx = threadIdx.x, ty = threadIdx.y;
    #pragma unroll
    for (int r = 0; r < 4; r++)
        t[ty + r * 8][tx] = src[(size_t)(k0 + ty + r * 8) * N + n0 + tx];
    __syncthreads();
    #pragma unroll
    for (int r = 0; r < 4; r++) {
        const float v = t[tx][ty + r * 8];
        const size_t o = (size_t)(n0 + ty + r * 8) * K + k0 + tx;
        splitw(v, dh + o, dl + o);
    }
}

// Fused Wq/Wk/Wv transpose+split into one [QKVN][KD] buffer. grid z picks src.
__global__ void wconv3(const float* __restrict__ s0, const float* __restrict__ s1,
                       const float* __restrict__ s2,
                       __nv_bfloat16* __restrict__ dh, __nv_bfloat16* __restrict__ dl)
{
    __shared__ float t[32][33];
    const float* src = (blockIdx.z == 0) ? s0 : (blockIdx.z == 1 ? s1 : s2);
    const int k0 = blockIdx.x * 32, n0 = blockIdx.y * 32;
    const int tx = threadIdx.x, ty = threadIdx.y;
    #pragma unroll
    for (int r = 0; r < 4; r++)
        t[ty + r * 8][tx] = src[(size_t)(k0 + ty + r * 8) * HK + n0 + tx];
    __syncthreads();
    const size_t rowoff = (size_t)blockIdx.z * HK;
    #pragma unroll
    for (int r = 0; r < 4; r++) {
        const float v = t[tx][ty + r * 8];
        const size_t o = (rowoff + n0 + ty + r * 8) * KD + k0 + tx;
        splitw(v, dh + o, dl + o);
    }
}

// ---------------------------------------------------------------------------
// V transpose+split per head from the fused QKV split buffer:
// v logical [b*t][12288] cols 8192.. -> vt [(b*8+h)*512+d][t].
// ---------------------------------------------------------------------------
__global__ void vconv2(const __nv_bfloat16* __restrict__ vh,
                       const __nv_bfloat16* __restrict__ vl,
                       __nv_bfloat16* __restrict__ dh, __nv_bfloat16* __restrict__ dl)
{
    __shared__ float t[32][33];
    const int z = blockIdx.z, b = z >> 3, h = z & 7;
    const int t0 = blockIdx.x * 32, d0 = blockIdx.y * 32;
    const int tx = threadIdx.x, ty = threadIdx.y;
    #pragma unroll
    for (int r = 0; r < 4; r++) {
        const size_t si = (size_t)(b * SEQ + t0 + ty + r * 8) * QKVN
                        + 2 * HK + h * KD + d0 + tx;
        t[ty + r * 8][tx] = __bfloat162float(vh[si]) + __bfloat162float(vl[si]);
    }
    __syncthreads();
    #pragma unroll
    for (int r = 0; r < 4; r++) {
        const float val = t[tx][ty + r * 8];
        const size_t o = ((size_t)z * KD + d0 + ty + r * 8) * SEQ + t0 + tx;
        splitw(val, dh + o, dl + o);
    }
}

// ---------------------------------------------------------------------------
// Embedding + positional encoding (+ split).
// ---------------------------------------------------------------------------
__global__ void embed_k(const int* __restrict__ x, const float* __restrict__ W,
                        float* __restrict__ h,
                        __nv_bfloat16* __restrict__ hh, __nv_bfloat16* __restrict__ hl)
{
    const int token = blockIdx.x;
    const int t  = token & (SEQ - 1);
    const int id = x[token];
    const int tid = threadIdx.x;
    #pragma unroll
    for (int u = 0; u < 2; u++) {
        const int c = tid + u * 256;
        const int j = c >> 1;
        const float ang = (float)t * expf(-(float)j * 0.07195578415606394f);
        const float p = (c & 1) ? cosf(ang) : sinf(ang);
        const float val = W[(size_t)id * KD + c] + p;
        const size_t o = (size_t)token * KD + c;
        h[o] = val;
        splitw(val, hh + o, hl + o);
    }
}

// ---------------------------------------------------------------------------
// Causal softmax (scale folded), writes split bf16. grid(SEQ, 32), 256 thr.
// ---------------------------------------------------------------------------
__global__ void softmax_k(const float* __restrict__ att,
                          __nv_bfloat16* __restrict__ oh, __nv_bfloat16* __restrict__ ol)
{
    const int q  = blockIdx.x;
    const int bh = blockIdx.y;
    const size_t base = ((size_t)bh * SEQ + q) * SEQ;
    const int tid = threadIdx.x;
    const float scale = 0.04419417382415922f;  // 1/sqrt(512)
    __shared__ float red[256];

    const float s0 = (tid       <= q) ? att[base + tid]       * scale : -3.4e38f;
    const float s1 = (tid + 256 <= q) ? att[base + tid + 256] * scale : -3.4e38f;
    red[tid] = fmaxf(s0, s1);
    __syncthreads();
    for (int o = 128; o; o >>= 1) {
        if (tid < o) red[tid] = fmaxf(red[tid], red[tid + o]);
        __syncthreads();
    }
    const float m = red[0];
    __syncthreads();
    const float v0 = (tid       <= q) ? expf(s0 - m) : 0.f;
    const float v1 = (tid + 256 <= q) ? expf(s1 - m) : 0.f;
    red[tid] = v0 + v1;
    __syncthreads();
    for (int o = 128; o; o >>= 1) {
        if (tid < o) red[tid] += red[tid + o];
        __syncthreads();
    }
    const float inv = 1.0f / red[0];
    splitw(v0 * inv, oh + base + tid,       ol + base + tid);
    splitw(v1 * inv, oh + base + tid + 256, ol + base + tid + 256);
}

// ---------------------------------------------------------------------------
// (optional residual) + LayerNorm (+ split).
// ---------------------------------------------------------------------------
__global__ void ln_k(const float* __restrict__ src, float* __restrict__ h,
                     __nv_bfloat16* __restrict__ hh, __nv_bfloat16* __restrict__ hl,
                     const float* __restrict__ w, const float* __restrict__ b,
                     int residual)
{
    const int token = blockIdx.x;
    const size_t base = (size_t)token * KD;
    const int tid = threadIdx.x;
    float x0 = src[base + tid];
    float x1 = src[base + tid + 256];
    if (residual) { x0 += h[base + tid]; x1 += h[base + tid + 256]; }
    __shared__ float s1[256], s2[256];
    s1[tid] = x0 + x1;
    s2[tid] = x0 * x0 + x1 * x1;
    __syncthreads();
    for (int o = 128; o; o >>= 1) {
        if (tid < o) { s1[tid] += s1[tid + o]; s2[tid] += s2[tid + o]; }
        __syncthreads();
    }
    const float mean = s1[0] * (1.f / KD);
    const float var  = s2[0] * (1.f / KD) - mean * mean;
    const float r = rsqrtf(var + 1e-5f);
    const float y0 = (x0 - mean) * r * w[tid]       + b[tid];
    const float y1 = (x1 - mean) * r * w[tid + 256] + b[tid + 256];
    h[base + tid]       = y0;
    h[base + tid + 256] = y1;
    splitw(y0, hh + base + tid,       hl + base + tid);
    splitw(y1, hh + base + tid + 256, hl + base + tid + 256);
}

// ---------------------------------------------------------------------------
// Host-side launcher
// ---------------------------------------------------------------------------
struct GemmArgs {
    const __nv_bfloat16 *Ah, *Al, *Bh, *Bl;
    const float* bias;
    float* C;
    __nv_bfloat16 *Ch, *Cl;
    int M, N, K, lda, ldb, ldc;
    long aO, aI, bO, bI, cO, cI;
    int zdiv, batches, causal;
};

template<int EPI, int OUT>
static void launch_gemm(const GemmArgs& a)
{
    static bool attr_set = false;
    if (!attr_set) {
        cudaFuncSetAttribute(gemm_ps<EPI, OUT>,
                             cudaFuncAttributeMaxDynamicSharedMemorySize, GEMM_SMEM);
        attr_set = true;
    }
    dim3 grid(a.N / 128, a.M / 128, a.batches), block(256);
    gemm_ps<EPI, OUT><<<grid, block, GEMM_SMEM>>>(
        a.Ah, a.Al, a.Bh, a.Bl, a.bias, a.C, a.Ch, a.Cl,
        a.M, a.N, a.K, a.lda, a.ldb, a.ldc,
        a.aO, a.aI, a.bO, a.bI, a.cO, a.cI, a.zdiv, a.causal);
}

extern "C" void kernel_launch(void* const* d_in, const int* in_sizes, int n_in,
                              void* d_out, int out_size)
{
    const int*   x        = (const int*)  d_in[0];
    const float* embed_W  = (const float*)d_in[1];
    const float* Wq       = (const float*)d_in[2];
    const float* Wk       = (const float*)d_in[3];
    const float* Wv       = (const float*)d_in[4];
    const float* Wu       = (const float*)d_in[5];
    const float* bu       = (const float*)d_in[6];
    const float* W1       = (const float*)d_in[7];
    const float* b1       = (const float*)d_in[8];
    const float* W2       = (const float*)d_in[9];
    const float* b2       = (const float*)d_in[10];
    const float* ln1_w    = (const float*)d_in[11];
    const float* ln1_b    = (const float*)d_in[12];
    const float* ln2_w    = (const float*)d_in[13];
    const float* ln2_b    = (const float*)d_in[14];
    const float* lnf_w    = (const float*)d_in[15];
    const float* lnf_b    = (const float*)d_in[16];
    const float* unembedW = (const float*)d_in[17];
    const float* unembedB = (const float*)d_in[18];
    float* out = (float*)d_out;

    float *h, *att, *tmp;
    __nv_bfloat16 *hsh, *hsl, *wth, *wtl, *qvh, *qvl,
                  *vth, *vtl, *ash, *asl, *ysh, *ysl, *fsh, *fsl;
    cudaGetSymbolAddress((void**)&h,   g_h);
    cudaGetSymbolAddress((void**)&att, g_att);
    cudaGetSymbolAddress((void**)&tmp, g_tmp);
    cudaGetSymbolAddress((void**)&hsh, g_hs_h); cudaGetSymbolAddress((void**)&hsl, g_hs_l);
    cudaGetSymbolAddress((void**)&wth, g_wt_h); cudaGetSymbolAddress((void**)&wtl, g_wt_l);
    cudaGetSymbolAddress((void**)&qvh, g_qkv_h); cudaGetSymbolAddress((void**)&qvl, g_qkv_l);
    cudaGetSymbolAddress((void**)&vth, g_vt_h); cudaGetSymbolAddress((void**)&vtl, g_vt_l);
    cudaGetSymbolAddress((void**)&ash, g_as_h); cudaGetSymbolAddress((void**)&asl, g_as_l);
    cudaGetSymbolAddress((void**)&ysh, g_ys_h); cudaGetSymbolAddress((void**)&ysl, g_ys_l);
    cudaGetSymbolAddress((void**)&fsh, g_fs_h); cudaGetSymbolAddress((void**)&fsl, g_fs_l);

    embed_k<<<MTOK, 256>>>(x, embed_W, h, hsh, hsl);

    const long atI = (long)SEQ * SEQ;          // 262144
    const long atO = (long)HEADS * atI;

    for (int i = 0; i < NBLK; i++) {
        const float* Wq_i = Wq + (size_t)i * KD * HK;
        const float* Wk_i = Wk + (size_t)i * KD * HK;
        const float* Wv_i = Wv + (size_t)i * KD * HK;
        const float* Wu_i = Wu + (size_t)i * HK * KD;
        const float* bu_i = bu + (size_t)i * KD;
        const float* W1_i = W1 + (size_t)i * KD * FF;
        const float* b1_i = b1 + (size_t)i * FF;
        const float* W2_i = W2 + (size_t)i * FF * KD;
        const float* b2_i = b2 + (size_t)i * KD;

        // fused QKV: weights -> [12288][512] split, then one wide GEMM
        wconv3<<<dim3(KD/32, HK/32, 3), dim3(32,8)>>>(Wq_i, Wk_i, Wv_i, wth, wtl);
        { GemmArgs a = {hsh, hsl, wth, wtl, nullptr, nullptr, qvh, qvl,
                        MTOK, QKVN, KD, KD, KD, QKVN, 0,0,0,0,0,0, 1, 1, 0};
          launch_gemm<0,1>(a); }

        // scores = Q @ K^T   (z = b*8+h); skip upper-triangle tiles
        { GemmArgs a = {qvh, qvl, qvh + HK, qvl + HK, nullptr, att, nullptr, nullptr,
                        SEQ, SEQ, KD, QKVN, QKVN, SEQ,
                        (long)SEQ*QKVN, (long)KD, (long)SEQ*QKVN, (long)KD,
                        atO, atI, HEADS, NBH, 1};
          launch_gemm<0,0>(a); }

        softmax_k<<<dim3(SEQ, NBH), 256>>>(att, ash, asl);
        vconv2<<<dim3(16,16,NBH), dim3(32,8)>>>(qvh, qvl, vth, vtl);

        // y = att @ V; truncate K per tile row (causal zeros)
        { GemmArgs a = {ash, asl, vth, vtl, nullptr, nullptr, ysh, ysl,
                        SEQ, KD, SEQ, SEQ, SEQ, HK,
                        atO, atI, atO, atI,
                        (long)SEQ*HK, (long)KD, HEADS, NBH, 2};
          launch_gemm<0,1>(a); }

        // proj: split-K=4 (slices of 1024) -> partials in att -> reduce+bias
        wconv<<<dim3(HK/32, KD/32), dim3(32,8)>>>(Wu_i, wth, wtl, HK, KD);
        { GemmArgs a = {ysh, ysl, wth, wtl, nullptr, att, nullptr, nullptr,
                        MTOK, KD, 1024, HK, HK, KD,
                        1024, 0, 1024, 0, (long)MTOK*KD, 0, 1, 4, 0};
          launch_gemm<0,0>(a); }
        reduce_k<<<(MTOK*KD/4 + 255)/256, 256>>>(att, bu_i, tmp, KD, MTOK*KD/4);

        ln_k<<<MTOK, 256>>>(tmp, h, hsh, hsl,
                            ln1_w + (size_t)i * KD, ln1_b + (size_t)i * KD, 1);

        // ff = gelu(h @ W1 + b1)   (split output)
        wconv<<<dim3(KD/32, FF/32), dim3(32,8)>>>(W1_i, wth, wtl, KD, FF);
        { GemmArgs a = {hsh, hsl, wth, wtl, b1_i, nullptr, fsh, fsl,
                        MTOK, FF, KD, KD, KD, FF, 0,0,0,0,0,0, 1, 1, 0};
          launch_gemm<2,1>(a); }

        // tmp = ff @ W2 + b2: split-K=4 (slices of 512) -> partials -> reduce
        wconv<<<dim3(FF/32, KD/32), dim3(32,8)>>>(W2_i, wth, wtl, FF, KD);
        { GemmArgs a = {fsh, fsl, wth, wtl, nullptr, att, nullptr, nullptr,
                        MTOK, KD, 512, FF, FF, KD,
                        512, 0, 512, 0, (long)MTOK*KD, 0, 1, 4, 0};
          launch_gemm<0,0>(a); }
        reduce_k<<<(MTOK*KD/4 + 255)/256, 256>>>(att, b2_i, tmp, KD, MTOK*KD/4);

        ln_k<<<MTOK, 256>>>(tmp, h, hsh, hsl,
                            ln2_w + (size_t)i * KD, ln2_b + (size_t)i * KD, 1);
    }

    ln_k<<<MTOK, 256>>>(h, h, hsh, hsl, lnf_w, lnf_b, 0);

    // unembed
    wconv<<<dim3(KD/32, VOCAB/32), dim3(32,8)>>>(unembedW, wth, wtl, KD, VOCAB);
    { GemmArgs a = {hsh, hsl, wth, wtl, unembedB, out, nullptr, nullptr,
                    MTOK, VOCAB, KD, KD, KD, VOCAB, 0,0,0,0,0,0, 1, 1, 0};
      launch_gemm<1,0>(a); }
}